// round 3
// baseline (speedup 1.0000x reference)
#include <cuda_runtime.h>
#include <math.h>

#define BB   1024
#define NA   32
#define DZ   96
#define DAA  32
#define DD   128
#define NE   8
#define FF   1024
#define XP   132   // activation tile pitch (floats), %4==0 for float4

// -------- global scratch (no allocations allowed) --------
__device__ float g_yp[2][BB][NA * DD];   // per-slot expert outputs
__device__ float g_h2[BB][512];          // head hidden
__device__ int   g_topi[BB][2];
__device__ float g_topg[BB][2];
__device__ float g_lse[BB];

// ============================ helpers ============================

__device__ __forceinline__ float warp_sum(float s) {
#pragma unroll
    for (int off = 16; off; off >>= 1) s += __shfl_xor_sync(0xffffffffu, s, off);
    return s;
}

// acc[r*8+c] += sum_d x[(na0+r)*XP+d] * Wg[(m0+c)*ldw + d]
// Weights read straight from gmem (L1-broadcast across the 16 tx-sharing threads).
__device__ __forceinline__ void mm_gl(const float* __restrict__ xsm,
                                      const float* __restrict__ Wg, int ldw,
                                      int na0, int m0, float acc[16]) {
    const float4* x0 = reinterpret_cast<const float4*>(xsm + na0 * XP);
    const float4* x1 = reinterpret_cast<const float4*>(xsm + (na0 + 1) * XP);
    const float* wbase = Wg + (size_t)m0 * ldw;
#pragma unroll 2
    for (int dt = 0; dt < 32; dt++) {
        float4 a0 = x0[dt];
        float4 a1 = x1[dt];
#pragma unroll
        for (int c = 0; c < 8; c++) {
            float4 w = *reinterpret_cast<const float4*>(wbase + (size_t)c * ldw + dt * 4);
            acc[c]     += a0.x * w.x + a0.y * w.y + a0.z * w.z + a0.w * w.w;
            acc[8 + c] += a1.x * w.x + a1.y * w.y + a1.z * w.z + a1.w * w.w;
        }
    }
}

// in-place layernorm over rows of buf[32][XP] (D=128), 8 warps / 32 rows
__device__ __forceinline__ void block_ln(float* buf, const float* __restrict__ g,
                                         const float* __restrict__ bt, int t) {
    int w = t >> 5, lane = t & 31;
    for (int row = w; row < 32; row += 8) {
        float* base = buf + row * XP;
        float v0 = base[lane], v1 = base[lane + 32], v2 = base[lane + 64], v3 = base[lane + 96];
        float mu = warp_sum(v0 + v1 + v2 + v3) * (1.f / 128.f);
        float d0 = v0 - mu, d1 = v1 - mu, d2 = v2 - mu, d3 = v3 - mu;
        float var = warp_sum(d0 * d0 + d1 * d1 + d2 * d2 + d3 * d3) * (1.f / 128.f);
        float rs = rsqrtf(var + 1e-5f);
        base[lane]      = d0 * rs * g[lane]      + bt[lane];
        base[lane + 32] = d1 * rs * g[lane + 32] + bt[lane + 32];
        base[lane + 64] = d2 * rs * g[lane + 64] + bt[lane + 64];
        base[lane + 96] = d3 * rs * g[lane + 96] + bt[lane + 96];
    }
}

// ============================ router ============================

__global__ void __launch_bounds__(256) router_kernel(const float* __restrict__ z,
                                                     const float* __restrict__ a,
                                                     const float* __restrict__ wg,
                                                     float* __restrict__ gates_out) {
    int b = blockIdx.x, t = threadIdx.x;
    float acc[8];
#pragma unroll
    for (int e = 0; e < 8; e++) acc[e] = 0.f;

    for (int i = t; i < NA * DD; i += 256) {
        int na = i >> 7, d = i & 127;
        float xv = (d < DZ) ? z[(b * NA + na) * DZ + d] : a[(b * NA + na) * DAA + (d - DZ)];
        const float4* wr = reinterpret_cast<const float4*>(wg + (size_t)i * 8);
        float4 w0 = wr[0], w1 = wr[1];
        acc[0] += xv * w0.x; acc[1] += xv * w0.y; acc[2] += xv * w0.z; acc[3] += xv * w0.w;
        acc[4] += xv * w1.x; acc[5] += xv * w1.y; acc[6] += xv * w1.z; acc[7] += xv * w1.w;
    }

    __shared__ float sred[8 * 8];
    __shared__ float lgs[8];
    int w = t >> 5, lane = t & 31;
#pragma unroll
    for (int e = 0; e < 8; e++) {
        float s = warp_sum(acc[e]);
        if (lane == 0) sred[w * 8 + e] = s;
    }
    __syncthreads();
    if (t < 8) {
        float s = 0.f;
#pragma unroll
        for (int ww = 0; ww < 8; ww++) s += sred[ww * 8 + t];
        lgs[t] = s;
    }
    __syncthreads();
    if (t == 0) {
        float m = lgs[0];
#pragma unroll
        for (int e = 1; e < 8; e++) m = fmaxf(m, lgs[e]);
        float se = 0.f;
#pragma unroll
        for (int e = 0; e < 8; e++) se += expf(lgs[e] - m);
        g_lse[b] = logf(se) + m;

        int i0 = 0; float v0 = lgs[0];
#pragma unroll
        for (int e = 1; e < 8; e++) if (lgs[e] > v0) { v0 = lgs[e]; i0 = e; }
        int i1 = -1; float v1 = -1e30f;
#pragma unroll
        for (int e = 0; e < 8; e++) if (e != i0 && lgs[e] > v1) { v1 = lgs[e]; i1 = e; }

        float ex = expf(v1 - v0);
        float inv = 1.f / (1.f + ex);
        float g0 = inv, g1 = ex * inv;
#pragma unroll
        for (int e = 0; e < 8; e++) gates_out[b * 8 + e] = 0.f;
        gates_out[b * 8 + i0] = g0;
        gates_out[b * 8 + i1] = g1;
        g_topi[b][0] = i0; g_topi[b][1] = i1;
        g_topg[b][0] = g0; g_topg[b][1] = g1;
    }
}

// ============================ expert ============================
// smem: 6 activation buffers of 32*XP floats
#define TPF (32 * XP)
#define EXPERT_SMEM_FLOATS (6 * TPF)
#define EXPERT_SMEM_BYTES  (EXPERT_SMEM_FLOATS * 4)

__global__ void __launch_bounds__(256) expert_kernel(
    const float* __restrict__ z,    const float* __restrict__ a,
    const float* __restrict__ w_in, const float* __restrict__ b_in,
    const float* __restrict__ w_out,const float* __restrict__ b_out,
    const float* __restrict__ ln1g, const float* __restrict__ ln1b,
    const float* __restrict__ w1,   const float* __restrict__ b1,
    const float* __restrict__ w2,   const float* __restrict__ b2,
    const float* __restrict__ ln2g, const float* __restrict__ ln2b) {
    extern __shared__ float sm[];
    float* xs = sm;
    float* qs = sm + TPF;
    float* ks = sm + 2 * TPF;
    float* vs = sm + 3 * TPF;
    float* hs = sm + 4 * TPF;
    float* fs = sm + 5 * TPF;

    int t = threadIdx.x;
    int bid = blockIdx.x;
    int b = bid >> 1, s = bid & 1;
    int e = g_topi[b][s];
    float gate = g_topg[b][s];
    int tx = t & 15, ty = t >> 4;
    int m0 = tx * 8, na0 = ty * 2;

    // ---- load x = concat(z, a) ----
    for (int i = t; i < NA * DD; i += 256) {
        int na = i >> 7, d = i & 127;
        float xv = (d < DZ) ? z[(b * NA + na) * DZ + d] : a[(b * NA + na) * DAA + (d - DZ)];
        xs[na * XP + d] = xv;
    }
    __syncthreads();

    // ---- qkv = x @ wi^T + bi ----
    const float* wi = w_in + (size_t)e * 384 * 128;
    const float* bi = b_in + (size_t)e * 384;
    float* outs[3] = {qs, ks, vs};
#pragma unroll
    for (int tile = 0; tile < 3; tile++) {
        float acc[16];
#pragma unroll
        for (int i = 0; i < 16; i++) acc[i] = 0.f;
        mm_gl(xs, wi + (size_t)tile * 128 * 128, 128, na0, m0, acc);
#pragma unroll
        for (int r = 0; r < 2; r++)
#pragma unroll
            for (int c = 0; c < 8; c++)
                outs[tile][(na0 + r) * XP + m0 + c] = acc[r * 8 + c] + bi[tile * 128 + m0 + c];
    }
    __syncthreads();

    // ---- attention scores (4 heads x 32 x 32) -> fs ----
    const float scale = 0.17677669529663687f;  // 1/sqrt(32)
    for (int i = t; i < 4096; i += 256) {
        int h = i >> 10, qi = (i >> 5) & 31, kj = i & 31;
        const float4* qp = reinterpret_cast<const float4*>(qs + qi * XP + h * 32);
        const float4* kp = reinterpret_cast<const float4*>(ks + kj * XP + h * 32);
        float acc = 0.f;
#pragma unroll
        for (int d = 0; d < 8; d++) {
            float4 qv = qp[d], kv = kp[d];
            acc += qv.x * kv.x + qv.y * kv.y + qv.z * kv.z + qv.w * kv.w;
        }
        fs[i] = acc * scale;
    }
    __syncthreads();
    // ---- softmax rows ----
    if (t < 128) {
        float* row = fs + t * 32;
        float m = row[0];
#pragma unroll
        for (int j = 1; j < 32; j++) m = fmaxf(m, row[j]);
        float ssum = 0.f;
#pragma unroll
        for (int j = 0; j < 32; j++) { float ee = expf(row[j] - m); row[j] = ee; ssum += ee; }
        float inv = 1.f / ssum;
#pragma unroll
        for (int j = 0; j < 32; j++) row[j] *= inv;
    }
    __syncthreads();
    // ---- o = att @ v  -> qs (overwrite) ----
    for (int i = t; i < 1024; i += 256) {
        int na = i >> 5, cg = i & 31;       // c = cg*4
        int h = cg >> 3, jl = (cg & 7) * 4; // within-head col
        const float* ap = fs + (h * 32 + na) * 32;
        float4 acc4 = make_float4(0.f, 0.f, 0.f, 0.f);
#pragma unroll 8
        for (int k = 0; k < 32; k++) {
            float av = ap[k];
            float4 vv = *reinterpret_cast<const float4*>(vs + k * XP + h * 32 + jl);
            acc4.x += av * vv.x; acc4.y += av * vv.y;
            acc4.z += av * vv.z; acc4.w += av * vv.w;
        }
        *reinterpret_cast<float4*>(qs + na * XP + cg * 4) = acc4;
    }
    __syncthreads();

    // ---- o-proj + residual -> hs ----
    {
        float acc[16];
#pragma unroll
        for (int i = 0; i < 16; i++) acc[i] = 0.f;
        mm_gl(qs, w_out + (size_t)e * 128 * 128, 128, na0, m0, acc);
        const float* bo = b_out + (size_t)e * 128;
#pragma unroll
        for (int r = 0; r < 2; r++)
#pragma unroll
            for (int c = 0; c < 8; c++)
                hs[(na0 + r) * XP + m0 + c] =
                    acc[r * 8 + c] + bo[m0 + c] + xs[(na0 + r) * XP + m0 + c];
    }
    __syncthreads();

    // ---- LN1 ----
    block_ln(hs, ln1g + (size_t)e * 128, ln1b + (size_t)e * 128, t);
    __syncthreads();

    // ---- FFN ----
    const float* W1 = w1 + (size_t)e * FF * DD;
    const float* B1 = b1 + (size_t)e * FF;
    const float* W2 = w2 + (size_t)e * DD * FF;
    const float* B2 = b2 + (size_t)e * DD;
    float facc[16];
#pragma unroll
    for (int i = 0; i < 16; i++) facc[i] = 0.f;

    for (int ft = 0; ft < 8; ft++) {
        float tacc[16];
#pragma unroll
        for (int i = 0; i < 16; i++) tacc[i] = 0.f;
        mm_gl(hs, W1 + (size_t)ft * 128 * 128, 128, na0, m0, tacc);
#pragma unroll
        for (int r = 0; r < 2; r++)
#pragma unroll
            for (int c = 0; c < 8; c++) {
                float v = tacc[r * 8 + c] + B1[ft * 128 + m0 + c];
                fs[(na0 + r) * XP + m0 + c] = fmaxf(v, 0.f);
            }
        __syncthreads();
        // W2 chunk: out d = m0+c, reduction over f-local (ldw = FF, base col ft*128)
        mm_gl(fs, W2 + ft * 128, FF, na0, m0, facc);
        __syncthreads();
    }

    // ---- epilogue: +bias +residual -> fs ----
#pragma unroll
    for (int r = 0; r < 2; r++)
#pragma unroll
        for (int c = 0; c < 8; c++)
            fs[(na0 + r) * XP + m0 + c] =
                facc[r * 8 + c] + B2[m0 + c] + hs[(na0 + r) * XP + m0 + c];
    __syncthreads();

    // ---- LN2, scale by gate, write to per-slot scratch ----
    {
        int w = t >> 5, lane = t & 31;
        const float* g2  = ln2g + (size_t)e * 128;
        const float* be2 = ln2b + (size_t)e * 128;
        for (int row = w; row < 32; row += 8) {
            float* base = fs + row * XP;
            float v0 = base[lane], v1 = base[lane + 32], v2 = base[lane + 64], v3 = base[lane + 96];
            float mu = warp_sum(v0 + v1 + v2 + v3) * (1.f / 128.f);
            float d0 = v0 - mu, d1 = v1 - mu, d2 = v2 - mu, d3 = v3 - mu;
            float var = warp_sum(d0 * d0 + d1 * d1 + d2 * d2 + d3 * d3) * (1.f / 128.f);
            float rs = rsqrtf(var + 1e-5f);
            float* outp = &g_yp[s][b][row * 128];
            outp[lane]      = (d0 * rs * g2[lane]      + be2[lane])      * gate;
            outp[lane + 32] = (d1 * rs * g2[lane + 32] + be2[lane + 32]) * gate;
            outp[lane + 64] = (d2 * rs * g2[lane + 64] + be2[lane + 64]) * gate;
            outp[lane + 96] = (d3 * rs * g2[lane + 96] + be2[lane + 96]) * gate;
        }
    }
}

// ============================ head ============================
// grid (64, 4): x = 16-token tile, y = 128-hidden tile. Weights via direct LDG.
__global__ void __launch_bounds__(256) head1_kernel(const float* __restrict__ hw1,
                                                    const float* __restrict__ hb1) {
    __shared__ float ys[16 * XP];
    int t = threadIdx.x;
    int tok0 = blockIdx.x * 16;
    int hbase = blockIdx.y * 128;
    int tx = t & 15, ty = t >> 4;
    int h0 = tx * 8;

    float acc[8];
#pragma unroll
    for (int c = 0; c < 8; c++) acc[c] = 0.f;

    for (int kt = 0; kt < 32; kt++) {
        for (int i = t; i < 16 * 128; i += 256) {
            int tok = i >> 7, d = i & 127;
            int col = kt * 128 + d;
            ys[tok * XP + d] = g_yp[0][tok0 + tok][col] + g_yp[1][tok0 + tok][col];
        }
        __syncthreads();
        const float4* xr = reinterpret_cast<const float4*>(ys + ty * XP);
        const float* wb = hw1 + (size_t)(hbase + h0) * 4096 + kt * 128;
#pragma unroll 2
        for (int dt = 0; dt < 32; dt++) {
            float4 xv = xr[dt];
#pragma unroll
            for (int c = 0; c < 8; c++) {
                float4 w = *reinterpret_cast<const float4*>(wb + (size_t)c * 4096 + dt * 4);
                acc[c] += xv.x * w.x + xv.y * w.y + xv.z * w.z + xv.w * w.w;
            }
        }
        __syncthreads();
    }
#pragma unroll
    for (int c = 0; c < 8; c++) {
        int hh = hbase + h0 + c;
        g_h2[tok0 + ty][hh] = fmaxf(acc[c] + hb1[hh], 0.f);
    }
}

// grid BB, 128 threads: warp w computes output o=w for its token
__global__ void __launch_bounds__(128) head2_kernel(const float* __restrict__ hw2,
                                                    const float* __restrict__ hb2,
                                                    float* __restrict__ r_out) {
    int tok = blockIdx.x;
    int w = threadIdx.x >> 5, lane = threadIdx.x & 31;
    const float* hp = g_h2[tok];
    const float* wp = hw2 + (size_t)w * 512;
    float acc = 0.f;
#pragma unroll 4
    for (int j = lane; j < 512; j += 32) acc += hp[j] * wp[j];
    acc = warp_sum(acc);
    if (lane == 0) r_out[tok * 4 + w] = acc + hb2[w];
}

// ============================ loss ============================

__global__ void __launch_bounds__(256) loss_kernel(const float* __restrict__ gates,
                                                   float* __restrict__ loss_out) {
    int t = threadIdx.x;
    float imp[8], ld[8];
#pragma unroll
    for (int e = 0; e < 8; e++) { imp[e] = 0.f; ld[e] = 0.f; }
    float lsum = 0.f;
    for (int b = t; b < BB; b += 256) {
#pragma unroll
        for (int e = 0; e < 8; e++) {
            float g = gates[b * 8 + e];
            imp[e] += g;
            ld[e]  += (g > 0.f) ? 1.f : 0.f;
        }
        lsum += g_lse[b];
    }
    __shared__ float simp[8 * 8], sld[8 * 8], sls[8];
    int w = t >> 5, lane = t & 31;
#pragma unroll
    for (int e = 0; e < 8; e++) {
        float si = warp_sum(imp[e]);
        float sl = warp_sum(ld[e]);
        if (lane == 0) { simp[w * 8 + e] = si; sld[w * 8 + e] = sl; }
    }
    {
        float sl2 = warp_sum(lsum);
        if (lane == 0) sls[w] = sl2;
    }
    __syncthreads();
    if (t == 0) {
        float I[8], L[8];
        float ls = 0.f;
#pragma unroll
        for (int ww = 0; ww < 8; ww++) ls += sls[ww];
#pragma unroll
        for (int e = 0; e < 8; e++) {
            float si = 0.f, sl = 0.f;
#pragma unroll
            for (int ww = 0; ww < 8; ww++) { si += simp[ww * 8 + e]; sl += sld[ww * 8 + e]; }
            I[e] = si; L[e] = sl;
        }
        float mi = 0.f, ml = 0.f;
#pragma unroll
        for (int e = 0; e < 8; e++) { mi += I[e]; ml += L[e]; }
        mi *= (1.f / 8.f); ml *= (1.f / 8.f);
        float vi = 0.f, vl = 0.f;
#pragma unroll
        for (int e = 0; e < 8; e++) {
            vi += (I[e] - mi) * (I[e] - mi);
            vl += (L[e] - ml) * (L[e] - ml);
        }
        vi *= (1.f / 7.f); vl *= (1.f / 7.f);
        float cv2i = vi / (mi * mi + 1e-10f);
        float cv2l = vl / (ml * ml + 1e-10f);
        loss_out[0] = cv2i + cv2l + ls * (1.f / (float)BB);
    }
}

// ============================ launch ============================

extern "C" void kernel_launch(void* const* d_in, const int* in_sizes, int n_in,
                              void* d_out, int out_size) {
    const float* z      = (const float*)d_in[0];
    const float* a      = (const float*)d_in[1];
    const float* w_gate = (const float*)d_in[2];
    const float* w_in   = (const float*)d_in[3];
    const float* b_in   = (const float*)d_in[4];
    const float* w_out  = (const float*)d_in[5];
    const float* b_out  = (const float*)d_in[6];
    const float* ln1_g  = (const float*)d_in[7];
    const float* ln1_b  = (const float*)d_in[8];
    const float* w1     = (const float*)d_in[9];
    const float* b1     = (const float*)d_in[10];
    const float* w2     = (const float*)d_in[11];
    const float* b2     = (const float*)d_in[12];
    const float* ln2_g  = (const float*)d_in[13];
    const float* ln2_b  = (const float*)d_in[14];
    const float* hw1    = (const float*)d_in[15];
    const float* hb1    = (const float*)d_in[16];
    const float* hw2    = (const float*)d_in[17];
    const float* hb2    = (const float*)d_in[18];

    float* out       = (float*)d_out;
    float* r_out     = out;                    // [1024,4]
    float* gates_out = out + BB * 4;           // [1024,8]
    float* loss_out  = out + BB * 4 + BB * 8;  // scalar

    cudaFuncSetAttribute(expert_kernel, cudaFuncAttributeMaxDynamicSharedMemorySize,
                         EXPERT_SMEM_BYTES);

    router_kernel<<<BB, 256>>>(z, a, w_gate, gates_out);
    expert_kernel<<<BB * 2, 256, EXPERT_SMEM_BYTES>>>(z, a, w_in, b_in, w_out, b_out,
                                                      ln1_g, ln1_b, w1, b1, w2, b2,
                                                      ln2_g, ln2_b);
    head1_kernel<<<dim3(BB / 16, 4), 256>>>(hw1, hb1);
    head2_kernel<<<BB, 128>>>(hw2, hb2, r_out);
    loss_kernel<<<1, 256>>>(gates_out, loss_out);
}

// round 4
// speedup vs baseline: 4.6466x; 4.6466x over previous
#include <cuda_runtime.h>
#include <math.h>
#include <stdint.h>

#define BB   1024
#define NA   32
#define DZ   96
#define DAA  32
#define DD   128
#define NE   8
#define FF   1024
#define XP   132    // activation tile pitch (floats), %4==0 for float4
#define WPITCH 132  // staged weight row pitch (floats); 528B, 16B-aligned
#define WB   528    // WPITCH*4

// -------- global scratch (no allocations allowed) --------
__device__ float g_yp[2][BB][NA * DD];   // per-slot expert outputs
__device__ float g_h2[BB][512];          // head hidden
__device__ int   g_topi[BB][2];
__device__ float g_topg[BB][2];
__device__ float g_lse[BB];

// ============================ helpers ============================

__device__ __forceinline__ uint32_t smem_u32(const void* p) {
    uint32_t r;
    asm("{ .reg .u64 t; cvta.to.shared.u64 t, %1; cvt.u32.u64 %0, t; }" : "=r"(r) : "l"(p));
    return r;
}
__device__ __forceinline__ void cp16(uint32_t dst, const void* src) {
    asm volatile("cp.async.ca.shared.global [%0], [%1], 16;" :: "r"(dst), "l"(src) : "memory");
}
__device__ __forceinline__ void cp_commit() {
    asm volatile("cp.async.commit_group;" ::: "memory");
}
__device__ __forceinline__ void cp_wait1() {
    asm volatile("cp.async.wait_group 1;" ::: "memory");
}
__device__ __forceinline__ void cp_wait0() {
    asm volatile("cp.async.wait_group 0;" ::: "memory");
}

__device__ __forceinline__ float warp_sum(float s) {
#pragma unroll
    for (int off = 16; off; off >>= 1) s += __shfl_xor_sync(0xffffffffu, s, off);
    return s;
}

// Stage 64 d-columns (dqoff: 0 or 16 chunks of 16B) of a [128 x ldw] row-major
// weight block into wbuf[128][WPITCH]. Coalesced: warp covers 2 rows x 256B.
__device__ __forceinline__ void stage_half(uint32_t wbase, const float* __restrict__ Wg,
                                           int ldw, int dqoff, int t) {
    for (int i = t; i < 2048; i += 256) {
        int m = i >> 4;
        int dq = (i & 15) + dqoff;
        cp16(wbase + m * WB + dq * 16, Wg + (size_t)m * ldw + dq * 4);
    }
    cp_commit();
}

// acc[r*8+j] += sum_{d=d0}^{d0+63} x[(na0+r)*XP+d] * ws[(tx+16j)*WPITCH + d]
// Strided-column ownership: lanes tx=0..15 -> <=2-way bank conflicts on LDS.64.
__device__ __forceinline__ void mm_half(const float* __restrict__ xs,
                                        const float* __restrict__ ws,
                                        int na0, int tx, int d0, float acc[16]) {
    const float* xr0 = xs + na0 * XP + d0;
    const float* xr1 = xr0 + XP;
#pragma unroll
    for (int dd = 0; dd < 64; dd += 4) {
        float4 x0 = *reinterpret_cast<const float4*>(xr0 + dd);
        float4 x1 = *reinterpret_cast<const float4*>(xr1 + dd);
#pragma unroll
        for (int j = 0; j < 8; j++) {
            const float* wp = ws + (tx + 16 * j) * WPITCH + d0 + dd;
            float2 wa = *reinterpret_cast<const float2*>(wp);
            float2 wb = *reinterpret_cast<const float2*>(wp + 2);
            acc[j]     += x0.x * wa.x + x0.y * wa.y + x0.z * wb.x + x0.w * wb.y;
            acc[8 + j] += x1.x * wa.x + x1.y * wa.y + x1.z * wb.x + x1.w * wb.y;
        }
    }
}

// Full 128-k GEMM tile with cp.async pipelined halves.
// Caller must __syncthreads() before (protects wbuf + xs).
__device__ __forceinline__ void do_gemm(float* wsmem, uint32_t wbase,
                                        const float* __restrict__ xs,
                                        const float* __restrict__ Wg, int ldw,
                                        int t, int tx, int na0, float acc[16]) {
    stage_half(wbase, Wg, ldw, 0, t);
    stage_half(wbase, Wg, ldw, 16, t);
    cp_wait1();
    __syncthreads();
    mm_half(xs, wsmem, na0, tx, 0, acc);
    cp_wait0();
    __syncthreads();
    mm_half(xs, wsmem, na0, tx, 64, acc);
}

// in-place layernorm over rows of buf[32][XP] (D=128), 8 warps / 32 rows
__device__ __forceinline__ void block_ln(float* buf, const float* __restrict__ g,
                                         const float* __restrict__ bt, int t) {
    int w = t >> 5, lane = t & 31;
    for (int row = w; row < 32; row += 8) {
        float* base = buf + row * XP;
        float v0 = base[lane], v1 = base[lane + 32], v2 = base[lane + 64], v3 = base[lane + 96];
        float mu = warp_sum(v0 + v1 + v2 + v3) * (1.f / 128.f);
        float d0 = v0 - mu, d1 = v1 - mu, d2 = v2 - mu, d3 = v3 - mu;
        float var = warp_sum(d0 * d0 + d1 * d1 + d2 * d2 + d3 * d3) * (1.f / 128.f);
        float rs = rsqrtf(var + 1e-5f);
        base[lane]      = d0 * rs * g[lane]      + bt[lane];
        base[lane + 32] = d1 * rs * g[lane + 32] + bt[lane + 32];
        base[lane + 64] = d2 * rs * g[lane + 64] + bt[lane + 64];
        base[lane + 96] = d3 * rs * g[lane + 96] + bt[lane + 96];
    }
}

// ============================ router ============================

__global__ void __launch_bounds__(256) router_kernel(const float* __restrict__ z,
                                                     const float* __restrict__ a,
                                                     const float* __restrict__ wg,
                                                     float* __restrict__ gates_out) {
    int b = blockIdx.x, t = threadIdx.x;
    float acc[8];
#pragma unroll
    for (int e = 0; e < 8; e++) acc[e] = 0.f;

    for (int i = t; i < NA * DD; i += 256) {
        int na = i >> 7, d = i & 127;
        float xv = (d < DZ) ? z[(b * NA + na) * DZ + d] : a[(b * NA + na) * DAA + (d - DZ)];
        const float4* wr = reinterpret_cast<const float4*>(wg + (size_t)i * 8);
        float4 w0 = wr[0], w1 = wr[1];
        acc[0] += xv * w0.x; acc[1] += xv * w0.y; acc[2] += xv * w0.z; acc[3] += xv * w0.w;
        acc[4] += xv * w1.x; acc[5] += xv * w1.y; acc[6] += xv * w1.z; acc[7] += xv * w1.w;
    }

    __shared__ float sred[8 * 8];
    __shared__ float lgs[8];
    int w = t >> 5, lane = t & 31;
#pragma unroll
    for (int e = 0; e < 8; e++) {
        float s = warp_sum(acc[e]);
        if (lane == 0) sred[w * 8 + e] = s;
    }
    __syncthreads();
    if (t < 8) {
        float s = 0.f;
#pragma unroll
        for (int ww = 0; ww < 8; ww++) s += sred[ww * 8 + t];
        lgs[t] = s;
    }
    __syncthreads();
    if (t == 0) {
        float m = lgs[0];
#pragma unroll
        for (int e = 1; e < 8; e++) m = fmaxf(m, lgs[e]);
        float se = 0.f;
#pragma unroll
        for (int e = 0; e < 8; e++) se += expf(lgs[e] - m);
        g_lse[b] = logf(se) + m;

        int i0 = 0; float v0 = lgs[0];
#pragma unroll
        for (int e = 1; e < 8; e++) if (lgs[e] > v0) { v0 = lgs[e]; i0 = e; }
        int i1 = -1; float v1 = -1e30f;
#pragma unroll
        for (int e = 0; e < 8; e++) if (e != i0 && lgs[e] > v1) { v1 = lgs[e]; i1 = e; }

        float ex = expf(v1 - v0);
        float inv = 1.f / (1.f + ex);
        float g0 = inv, g1 = ex * inv;
#pragma unroll
        for (int e = 0; e < 8; e++) gates_out[b * 8 + e] = 0.f;
        gates_out[b * 8 + i0] = g0;
        gates_out[b * 8 + i1] = g1;
        g_topi[b][0] = i0; g_topi[b][1] = i1;
        g_topg[b][0] = g0; g_topg[b][1] = g1;
    }
}

// ============================ expert ============================
// smem: weight buffer [128][WPITCH] + 6 activation buffers [32][XP]
#define TPF (32 * XP)
#define WTF (128 * WPITCH)
#define EXPERT_SMEM_FLOATS (WTF + 6 * TPF)
#define EXPERT_SMEM_BYTES  (EXPERT_SMEM_FLOATS * 4)

__global__ void __launch_bounds__(256) expert_kernel(
    const float* __restrict__ z,    const float* __restrict__ a,
    const float* __restrict__ w_in, const float* __restrict__ b_in,
    const float* __restrict__ w_out,const float* __restrict__ b_out,
    const float* __restrict__ ln1g, const float* __restrict__ ln1b,
    const float* __restrict__ w1,   const float* __restrict__ b1,
    const float* __restrict__ w2,   const float* __restrict__ b2,
    const float* __restrict__ ln2g, const float* __restrict__ ln2b) {
    extern __shared__ float sm[];
    float* wsmem = sm;
    float* xs = sm + WTF;
    float* qs = xs + TPF;
    float* ks = xs + 2 * TPF;
    float* vs = xs + 3 * TPF;
    float* hs = xs + 4 * TPF;
    float* fs = xs + 5 * TPF;
    uint32_t wbase = smem_u32(wsmem);

    int t = threadIdx.x;
    int bid = blockIdx.x;
    int b = bid >> 1, s = bid & 1;
    int e = g_topi[b][s];
    float gate = g_topg[b][s];
    int tx = t & 15, ty = t >> 4;
    int na0 = ty * 2;

    // ---- load x = concat(z, a) ----
    for (int i = t; i < NA * DD; i += 256) {
        int na = i >> 7, d = i & 127;
        float xv = (d < DZ) ? z[(b * NA + na) * DZ + d] : a[(b * NA + na) * DAA + (d - DZ)];
        xs[na * XP + d] = xv;
    }
    __syncthreads();

    // ---- qkv = x @ wi^T + bi ----
    const float* wi = w_in + (size_t)e * 384 * 128;
    const float* bi = b_in + (size_t)e * 384;
    float* outs[3] = {qs, ks, vs};
#pragma unroll
    for (int tile = 0; tile < 3; tile++) {
        float acc[16];
#pragma unroll
        for (int i = 0; i < 16; i++) acc[i] = 0.f;
        do_gemm(wsmem, wbase, xs, wi + (size_t)tile * 128 * 128, 128, t, tx, na0, acc);
#pragma unroll
        for (int r = 0; r < 2; r++)
#pragma unroll
            for (int j = 0; j < 8; j++) {
                int m = tx + 16 * j;
                outs[tile][(na0 + r) * XP + m] = acc[r * 8 + j] + bi[tile * 128 + m];
            }
        __syncthreads();
    }

    // ---- attention scores (4 heads x 32 x 32) -> fs ----
    const float scale = 0.17677669529663687f;  // 1/sqrt(32)
    for (int i = t; i < 4096; i += 256) {
        int h = i >> 10, qi = (i >> 5) & 31, kj = i & 31;
        const float4* qp = reinterpret_cast<const float4*>(qs + qi * XP + h * 32);
        const float4* kp = reinterpret_cast<const float4*>(ks + kj * XP + h * 32);
        float acc = 0.f;
#pragma unroll
        for (int d = 0; d < 8; d++) {
            float4 qv = qp[d], kv = kp[d];
            acc += qv.x * kv.x + qv.y * kv.y + qv.z * kv.z + qv.w * kv.w;
        }
        fs[i] = acc * scale;
    }
    __syncthreads();
    // ---- softmax rows ----
    if (t < 128) {
        float* row = fs + t * 32;
        float m = row[0];
#pragma unroll
        for (int j = 1; j < 32; j++) m = fmaxf(m, row[j]);
        float ssum = 0.f;
#pragma unroll
        for (int j = 0; j < 32; j++) { float ee = expf(row[j] - m); row[j] = ee; ssum += ee; }
        float inv = 1.f / ssum;
#pragma unroll
        for (int j = 0; j < 32; j++) row[j] *= inv;
    }
    __syncthreads();
    // ---- o = att @ v  -> overwrite qs ----
    for (int i = t; i < 1024; i += 256) {
        int na = i >> 5, cg = i & 31;
        int h = cg >> 3, jl = (cg & 7) * 4;
        const float* ap = fs + (h * 32 + na) * 32;
        float4 acc4 = make_float4(0.f, 0.f, 0.f, 0.f);
#pragma unroll 8
        for (int k = 0; k < 32; k++) {
            float av = ap[k];
            float4 vv = *reinterpret_cast<const float4*>(vs + k * XP + h * 32 + jl);
            acc4.x += av * vv.x; acc4.y += av * vv.y;
            acc4.z += av * vv.z; acc4.w += av * vv.w;
        }
        *reinterpret_cast<float4*>(qs + na * XP + cg * 4) = acc4;
    }
    __syncthreads();

    // ---- o-proj + residual -> hs ----
    {
        float acc[16];
#pragma unroll
        for (int i = 0; i < 16; i++) acc[i] = 0.f;
        do_gemm(wsmem, wbase, qs, w_out + (size_t)e * 128 * 128, 128, t, tx, na0, acc);
        const float* bo = b_out + (size_t)e * 128;
#pragma unroll
        for (int r = 0; r < 2; r++)
#pragma unroll
            for (int j = 0; j < 8; j++) {
                int m = tx + 16 * j;
                hs[(na0 + r) * XP + m] = acc[r * 8 + j] + bo[m] + xs[(na0 + r) * XP + m];
            }
    }
    __syncthreads();

    // ---- LN1 ----
    block_ln(hs, ln1g + (size_t)e * 128, ln1b + (size_t)e * 128, t);
    __syncthreads();

    // ---- FFN ----
    const float* W1 = w1 + (size_t)e * FF * DD;
    const float* B1 = b1 + (size_t)e * FF;
    const float* W2 = w2 + (size_t)e * DD * FF;
    const float* B2 = b2 + (size_t)e * DD;
    float facc[16];
#pragma unroll
    for (int i = 0; i < 16; i++) facc[i] = 0.f;

    for (int ft = 0; ft < 8; ft++) {
        float tacc[16];
#pragma unroll
        for (int i = 0; i < 16; i++) tacc[i] = 0.f;
        do_gemm(wsmem, wbase, hs, W1 + (size_t)ft * 128 * 128, 128, t, tx, na0, tacc);
#pragma unroll
        for (int r = 0; r < 2; r++)
#pragma unroll
            for (int j = 0; j < 8; j++) {
                int m = tx + 16 * j;
                float v = tacc[r * 8 + j] + B1[ft * 128 + m];
                fs[(na0 + r) * XP + m] = fmaxf(v, 0.f);
            }
        __syncthreads();
        // W2 chunk: rows = output d (128), cols = f-local (ldw = FF, col base ft*128)
        do_gemm(wsmem, wbase, fs, W2 + ft * 128, FF, t, tx, na0, facc);
        __syncthreads();
    }

    // ---- epilogue: +bias +residual -> fs ----
#pragma unroll
    for (int r = 0; r < 2; r++)
#pragma unroll
        for (int j = 0; j < 8; j++) {
            int m = tx + 16 * j;
            fs[(na0 + r) * XP + m] = facc[r * 8 + j] + B2[m] + hs[(na0 + r) * XP + m];
        }
    __syncthreads();

    // ---- LN2, scale by gate, write to per-slot scratch ----
    {
        int w = t >> 5, lane = t & 31;
        const float* g2  = ln2g + (size_t)e * 128;
        const float* be2 = ln2b + (size_t)e * 128;
        for (int row = w; row < 32; row += 8) {
            float* base = fs + row * XP;
            float v0 = base[lane], v1 = base[lane + 32], v2 = base[lane + 64], v3 = base[lane + 96];
            float mu = warp_sum(v0 + v1 + v2 + v3) * (1.f / 128.f);
            float d0 = v0 - mu, d1 = v1 - mu, d2 = v2 - mu, d3 = v3 - mu;
            float var = warp_sum(d0 * d0 + d1 * d1 + d2 * d2 + d3 * d3) * (1.f / 128.f);
            float rs = rsqrtf(var + 1e-5f);
            float* outp = &g_yp[s][b][row * 128];
            outp[lane]      = (d0 * rs * g2[lane]      + be2[lane])      * gate;
            outp[lane + 32] = (d1 * rs * g2[lane + 32] + be2[lane + 32]) * gate;
            outp[lane + 64] = (d2 * rs * g2[lane + 64] + be2[lane + 64]) * gate;
            outp[lane + 96] = (d3 * rs * g2[lane + 96] + be2[lane + 96]) * gate;
        }
    }
}

// ============================ head ============================
// grid (64, 4): x = 16-token tile, y = 128-hidden tile. Staged weights.
#define HEAD_SMEM_FLOATS (WTF + 16 * XP)
#define HEAD_SMEM_BYTES  (HEAD_SMEM_FLOATS * 4)

__global__ void __launch_bounds__(256, 2) head1_kernel(const float* __restrict__ hw1,
                                                       const float* __restrict__ hb1) {
    extern __shared__ float sm[];
    float* wsmem = sm;
    float* ys = sm + WTF;   // [16][XP]
    uint32_t wbase = smem_u32(wsmem);

    int t = threadIdx.x;
    int tok0 = blockIdx.x * 16;
    int hbase = blockIdx.y * 128;
    int tx = t & 15, ty = t >> 4;   // ty = token 0..15

    float acc[8];
#pragma unroll
    for (int c = 0; c < 8; c++) acc[c] = 0.f;

    for (int kt = 0; kt < 32; kt++) {
        __syncthreads();   // wbuf + ys free for reuse
        const float* Wg = hw1 + (size_t)hbase * 4096 + kt * 128;
        stage_half(wbase, Wg, 4096, 0, t);
        stage_half(wbase, Wg, 4096, 16, t);
        // overlap ys fill with cp.async latency
        for (int i = t; i < 16 * 128; i += 256) {
            int tok = i >> 7, d = i & 127;
            int col = kt * 128 + d;
            ys[tok * XP + d] = g_yp[0][tok0 + tok][col] + g_yp[1][tok0 + tok][col];
        }
        cp_wait1();
        __syncthreads();
        // compute d 0..63
        const float* xr = ys + ty * XP;
#pragma unroll
        for (int dd = 0; dd < 64; dd += 4) {
            float4 xv = *reinterpret_cast<const float4*>(xr + dd);
#pragma unroll
            for (int j = 0; j < 8; j++) {
                const float* wp = wsmem + (tx + 16 * j) * WPITCH + dd;
                float2 wa = *reinterpret_cast<const float2*>(wp);
                float2 wb = *reinterpret_cast<const float2*>(wp + 2);
                acc[j] += xv.x * wa.x + xv.y * wa.y + xv.z * wb.x + xv.w * wb.y;
            }
        }
        cp_wait0();
        __syncthreads();
#pragma unroll
        for (int dd = 64; dd < 128; dd += 4) {
            float4 xv = *reinterpret_cast<const float4*>(xr + dd);
#pragma unroll
            for (int j = 0; j < 8; j++) {
                const float* wp = wsmem + (tx + 16 * j) * WPITCH + dd;
                float2 wa = *reinterpret_cast<const float2*>(wp);
                float2 wb = *reinterpret_cast<const float2*>(wp + 2);
                acc[j] += xv.x * wa.x + xv.y * wa.y + xv.z * wb.x + xv.w * wb.y;
            }
        }
    }
#pragma unroll
    for (int j = 0; j < 8; j++) {
        int hh = hbase + tx + 16 * j;
        g_h2[tok0 + ty][hh] = fmaxf(acc[j] + hb1[hh], 0.f);
    }
}

// grid BB, 128 threads: warp w computes output o=w for its token
__global__ void __launch_bounds__(128) head2_kernel(const float* __restrict__ hw2,
                                                    const float* __restrict__ hb2,
                                                    float* __restrict__ r_out) {
    int tok = blockIdx.x;
    int w = threadIdx.x >> 5, lane = threadIdx.x & 31;
    const float* hp = g_h2[tok];
    const float* wp = hw2 + (size_t)w * 512;
    float acc = 0.f;
#pragma unroll 4
    for (int j = lane; j < 512; j += 32) acc += hp[j] * wp[j];
    acc = warp_sum(acc);
    if (lane == 0) r_out[tok * 4 + w] = acc + hb2[w];
}

// ============================ loss ============================

__global__ void __launch_bounds__(256) loss_kernel(const float* __restrict__ gates,
                                                   float* __restrict__ loss_out) {
    int t = threadIdx.x;
    float imp[8], ld[8];
#pragma unroll
    for (int e = 0; e < 8; e++) { imp[e] = 0.f; ld[e] = 0.f; }
    float lsum = 0.f;
    for (int b = t; b < BB; b += 256) {
#pragma unroll
        for (int e = 0; e < 8; e++) {
            float g = gates[b * 8 + e];
            imp[e] += g;
            ld[e]  += (g > 0.f) ? 1.f : 0.f;
        }
        lsum += g_lse[b];
    }
    __shared__ float simp[8 * 8], sld[8 * 8], sls[8];
    int w = t >> 5, lane = t & 31;
#pragma unroll
    for (int e = 0; e < 8; e++) {
        float si = warp_sum(imp[e]);
        float sl = warp_sum(ld[e]);
        if (lane == 0) { simp[w * 8 + e] = si; sld[w * 8 + e] = sl; }
    }
    {
        float sl2 = warp_sum(lsum);
        if (lane == 0) sls[w] = sl2;
    }
    __syncthreads();
    if (t == 0) {
        float I[8], L[8];
        float ls = 0.f;
#pragma unroll
        for (int ww = 0; ww < 8; ww++) ls += sls[ww];
#pragma unroll
        for (int e = 0; e < 8; e++) {
            float si = 0.f, sl = 0.f;
#pragma unroll
            for (int ww = 0; ww < 8; ww++) { si += simp[ww * 8 + e]; sl += sld[ww * 8 + e]; }
            I[e] = si; L[e] = sl;
        }
        float mi = 0.f, ml = 0.f;
#pragma unroll
        for (int e = 0; e < 8; e++) { mi += I[e]; ml += L[e]; }
        mi *= (1.f / 8.f); ml *= (1.f / 8.f);
        float vi = 0.f, vl = 0.f;
#pragma unroll
        for (int e = 0; e < 8; e++) {
            vi += (I[e] - mi) * (I[e] - mi);
            vl += (L[e] - ml) * (L[e] - ml);
        }
        vi *= (1.f / 7.f); vl *= (1.f / 7.f);
        float cv2i = vi / (mi * mi + 1e-10f);
        float cv2l = vl / (ml * ml + 1e-10f);
        loss_out[0] = cv2i + cv2l + ls * (1.f / (float)BB);
    }
}

// ============================ launch ============================

extern "C" void kernel_launch(void* const* d_in, const int* in_sizes, int n_in,
                              void* d_out, int out_size) {
    const float* z      = (const float*)d_in[0];
    const float* a      = (const float*)d_in[1];
    const float* w_gate = (const float*)d_in[2];
    const float* w_in   = (const float*)d_in[3];
    const float* b_in   = (const float*)d_in[4];
    const float* w_out  = (const float*)d_in[5];
    const float* b_out  = (const float*)d_in[6];
    const float* ln1_g  = (const float*)d_in[7];
    const float* ln1_b  = (const float*)d_in[8];
    const float* w1     = (const float*)d_in[9];
    const float* b1     = (const float*)d_in[10];
    const float* w2     = (const float*)d_in[11];
    const float* b2     = (const float*)d_in[12];
    const float* ln2_g  = (const float*)d_in[13];
    const float* ln2_b  = (const float*)d_in[14];
    const float* hw1    = (const float*)d_in[15];
    const float* hb1    = (const float*)d_in[16];
    const float* hw2    = (const float*)d_in[17];
    const float* hb2    = (const float*)d_in[18];

    float* out       = (float*)d_out;
    float* r_out     = out;                    // [1024,4]
    float* gates_out = out + BB * 4;           // [1024,8]
    float* loss_out  = out + BB * 4 + BB * 8;  // scalar

    cudaFuncSetAttribute(expert_kernel, cudaFuncAttributeMaxDynamicSharedMemorySize,
                         EXPERT_SMEM_BYTES);
    cudaFuncSetAttribute(head1_kernel, cudaFuncAttributeMaxDynamicSharedMemorySize,
                         HEAD_SMEM_BYTES);

    router_kernel<<<BB, 256>>>(z, a, w_gate, gates_out);
    expert_kernel<<<BB * 2, 256, EXPERT_SMEM_BYTES>>>(z, a, w_in, b_in, w_out, b_out,
                                                      ln1_g, ln1_b, w1, b1, w2, b2,
                                                      ln2_g, ln2_b);
    head1_kernel<<<dim3(BB / 16, 4), 256, HEAD_SMEM_BYTES>>>(hw1, hb1);
    head2_kernel<<<BB, 128>>>(hw2, hb2, r_out);
    loss_kernel<<<1, 256>>>(gates_out, loss_out);
}

// round 11
// speedup vs baseline: 5.2705x; 1.1343x over previous
#include <cuda_runtime.h>
#include <math.h>
#include <stdint.h>

#define BB   1024
#define NA   32
#define DZ   96
#define DAA  32
#define DD   128
#define NE   8
#define FF   1024
#define XP   132    // activation tile pitch (floats)
#define WPITCH 132  // head1 staged weight row pitch (floats)
#define WB   528    // WPITCH*4
#define CPITCH 68   // expert chunk buffer row pitch (floats), 272B (16B aligned)
#define CB   272    // CPITCH*4
#define CHUNK_F (128 * CPITCH)
#define NCHUNKS 40  // 20 tiles x 2 halves

// -------- global scratch (no allocations allowed) --------
__device__ float g_yp[2][BB][NA * DD];   // per-slot expert outputs
__device__ float g_h2[BB][512];          // head hidden
__device__ int   g_topi[BB][2];
__device__ float g_topg[BB][2];
__device__ float g_lse[BB];

// ============================ helpers ============================

__device__ __forceinline__ uint32_t smem_u32(const void* p) {
    uint32_t r;
    asm("{ .reg .u64 t; cvta.to.shared.u64 t, %1; cvt.u32.u64 %0, t; }" : "=r"(r) : "l"(p));
    return r;
}
__device__ __forceinline__ void cp16(uint32_t dst, const void* src) {
    asm volatile("cp.async.ca.shared.global [%0], [%1], 16;" :: "r"(dst), "l"(src) : "memory");
}
__device__ __forceinline__ void cp_commit() {
    asm volatile("cp.async.commit_group;" ::: "memory");
}
__device__ __forceinline__ void cp_wait1() {
    asm volatile("cp.async.wait_group 1;" ::: "memory");
}
__device__ __forceinline__ void cp_wait0() {
    asm volatile("cp.async.wait_group 0;" ::: "memory");
}

// packed f32x2 FMA: d.lo += a.lo*b.lo ; d.hi += a.hi*b.hi  (sm_103a FFMA2)
__device__ __forceinline__ void ffma2(unsigned long long& d,
                                      unsigned long long a, unsigned long long b) {
    asm("fma.rn.f32x2 %0, %1, %2, %0;" : "+l"(d) : "l"(a), "l"(b));
}
// horizontal sum of the two f32 lanes
__device__ __forceinline__ float psum(unsigned long long p) {
    float lo, hi;
    asm("mov.b64 {%0,%1}, %2;" : "=f"(lo), "=f"(hi) : "l"(p));
    return lo + hi;
}

__device__ __forceinline__ float warp_sum(float s) {
#pragma unroll
    for (int off = 16; off; off >>= 1) s += __shfl_xor_sync(0xffffffffu, s, off);
    return s;
}

// ---- head1 staging (full 128-col buffer, WPITCH rows) ----
__device__ __forceinline__ void stage_half(uint32_t wbase, const float* __restrict__ Wg,
                                           int ldw, int dqoff, int t) {
    for (int i = t; i < 2048; i += 256) {
        int m = i >> 4;
        int dq = (i & 15) + dqoff;
        cp16(wbase + m * WB + dq * 16, Wg + (size_t)m * ldw + dq * 4);
    }
    cp_commit();
}

// ---- expert: stage chunk c (tile c>>1, half c&1) into a 64-col chunk buffer ----
__device__ __forceinline__ void stage_next(int cidx, uint32_t dstbase, int e, int t,
                                           const float* __restrict__ w_in,
                                           const float* __restrict__ w_out,
                                           const float* __restrict__ w1,
                                           const float* __restrict__ w2) {
    if (cidx < NCHUNKS) {
        int tile = cidx >> 1, half = cidx & 1;
        const float* p;
        int ldw;
        if (tile < 3)       { p = w_in  + (size_t)e * 384 * 128 + (size_t)tile * 16384; ldw = 128; }
        else if (tile == 3) { p = w_out + (size_t)e * 16384; ldw = 128; }
        else if ((tile & 1) == 0) { int ft = (tile - 4) >> 1;
                              p = w1 + (size_t)e * FF * DD + (size_t)ft * 16384; ldw = 128; }
        else                { int ft = (tile - 4) >> 1;
                              p = w2 + (size_t)e * DD * FF + ft * 128; ldw = FF; }
        for (int i = t; i < 2048; i += 256) {
            int m = i >> 4, dq = i & 15;
            cp16(dstbase + m * CB + dq * 16, p + (size_t)m * ldw + (dq + half * 16) * 4);
        }
    }
    cp_commit();   // empty group when cidx >= NCHUNKS keeps accounting uniform
}

// packed half-GEMM: accp[r*8+j] lanes accumulate (even-k, odd-k) partial sums
__device__ __forceinline__ void mm_half_p(const float* __restrict__ xs, int xoff,
                                          const float* __restrict__ wb,
                                          int na0, int tx, unsigned long long accp[16]) {
    const float* xr0 = xs + na0 * XP + xoff;
    const float* xr1 = xr0 + XP;
#pragma unroll 4
    for (int dd = 0; dd < 64; dd += 4) {
        ulonglong2 x0 = *reinterpret_cast<const ulonglong2*>(xr0 + dd);
        ulonglong2 x1 = *reinterpret_cast<const ulonglong2*>(xr1 + dd);
#pragma unroll
        for (int j = 0; j < 8; j++) {
            ulonglong2 w = *reinterpret_cast<const ulonglong2*>(wb + (tx + 16 * j) * CPITCH + dd);
            ffma2(accp[j],     x0.x, w.x);
            ffma2(accp[j],     x0.y, w.y);
            ffma2(accp[8 + j], x1.x, w.x);
            ffma2(accp[8 + j], x1.y, w.y);
        }
    }
}

// one 128-k GEMM tile with 2-chunk rotating prefetch pipeline
__device__ __forceinline__ void gemm_tile(int& c, uint32_t bufu0, uint32_t bufu1,
                                          const float* __restrict__ buf0,
                                          const float* __restrict__ buf1,
                                          const float* __restrict__ xsrc,
                                          int t, int tx, int na0,
                                          unsigned long long accp[16], int e,
                                          const float* __restrict__ w_in,
                                          const float* __restrict__ w_out,
                                          const float* __restrict__ w1,
                                          const float* __restrict__ w2) {
#pragma unroll
    for (int h = 0; h < 2; h++) {
        cp_wait1();          // chunks <= c complete (one group may remain in flight)
        __syncthreads();
        const float* wb = (c & 1) ? buf1 : buf0;
        mm_half_p(xsrc, h * 64, wb, na0, tx, accp);
        __syncthreads();     // all readers done before refill
        stage_next(c + 2, (c & 1) ? bufu1 : bufu0, e, t, w_in, w_out, w1, w2);
        c++;
    }
}

// in-place layernorm over rows of buf[32][XP] (D=128), 8 warps / 32 rows
__device__ __forceinline__ void block_ln(float* buf, const float* __restrict__ g,
                                         const float* __restrict__ bt, int t) {
    int w = t >> 5, lane = t & 31;
    for (int row = w; row < 32; row += 8) {
        float* base = buf + row * XP;
        float v0 = base[lane], v1 = base[lane + 32], v2 = base[lane + 64], v3 = base[lane + 96];
        float mu = warp_sum(v0 + v1 + v2 + v3) * (1.f / 128.f);
        float d0 = v0 - mu, d1 = v1 - mu, d2 = v2 - mu, d3 = v3 - mu;
        float var = warp_sum(d0 * d0 + d1 * d1 + d2 * d2 + d3 * d3) * (1.f / 128.f);
        float rs = rsqrtf(var + 1e-5f);
        base[lane]      = d0 * rs * g[lane]      + bt[lane];
        base[lane + 32] = d1 * rs * g[lane + 32] + bt[lane + 32];
        base[lane + 64] = d2 * rs * g[lane + 64] + bt[lane + 64];
        base[lane + 96] = d3 * rs * g[lane + 96] + bt[lane + 96];
    }
}

// ============================ router ============================

__global__ void __launch_bounds__(256) router_kernel(const float* __restrict__ z,
                                                     const float* __restrict__ a,
                                                     const float* __restrict__ wg,
                                                     float* __restrict__ gates_out) {
    int b = blockIdx.x, t = threadIdx.x;
    float acc[8];
#pragma unroll
    for (int e = 0; e < 8; e++) acc[e] = 0.f;

    for (int i = t; i < NA * DD; i += 256) {
        int na = i >> 7, d = i & 127;
        float xv = (d < DZ) ? z[(b * NA + na) * DZ + d] : a[(b * NA + na) * DAA + (d - DZ)];
        const float4* wr = reinterpret_cast<const float4*>(wg + (size_t)i * 8);
        float4 w0 = wr[0], w1 = wr[1];
        acc[0] += xv * w0.x; acc[1] += xv * w0.y; acc[2] += xv * w0.z; acc[3] += xv * w0.w;
        acc[4] += xv * w1.x; acc[5] += xv * w1.y; acc[6] += xv * w1.z; acc[7] += xv * w1.w;
    }

    __shared__ float sred[8 * 8];
    __shared__ float lgs[8];
    int w = t >> 5, lane = t & 31;
#pragma unroll
    for (int e = 0; e < 8; e++) {
        float s = warp_sum(acc[e]);
        if (lane == 0) sred[w * 8 + e] = s;
    }
    __syncthreads();
    if (t < 8) {
        float s = 0.f;
#pragma unroll
        for (int ww = 0; ww < 8; ww++) s += sred[ww * 8 + t];
        lgs[t] = s;
    }
    __syncthreads();
    if (t == 0) {
        float m = lgs[0];
#pragma unroll
        for (int e = 1; e < 8; e++) m = fmaxf(m, lgs[e]);
        float se = 0.f;
#pragma unroll
        for (int e = 0; e < 8; e++) se += expf(lgs[e] - m);
        g_lse[b] = logf(se) + m;

        int i0 = 0; float v0 = lgs[0];
#pragma unroll
        for (int e = 1; e < 8; e++) if (lgs[e] > v0) { v0 = lgs[e]; i0 = e; }
        int i1 = -1; float v1 = -1e30f;
#pragma unroll
        for (int e = 0; e < 8; e++) if (e != i0 && lgs[e] > v1) { v1 = lgs[e]; i1 = e; }

        float ex = expf(v1 - v0);
        float inv = 1.f / (1.f + ex);
        float g0 = inv, g1 = ex * inv;
#pragma unroll
        for (int e = 0; e < 8; e++) gates_out[b * 8 + e] = 0.f;
        gates_out[b * 8 + i0] = g0;
        gates_out[b * 8 + i1] = g1;
        g_topi[b][0] = i0; g_topi[b][1] = i1;
        g_topg[b][0] = g0; g_topg[b][1] = g1;
    }
}

// ============================ expert ============================
// smem: 2 chunk buffers + 6 activation buffers [32][XP]
#define TPF (32 * XP)
#define EXPERT_SMEM_FLOATS (2 * CHUNK_F + 6 * TPF)
#define EXPERT_SMEM_BYTES  (EXPERT_SMEM_FLOATS * 4)

__global__ void __launch_bounds__(256) expert_kernel(
    const float* __restrict__ z,    const float* __restrict__ a,
    const float* __restrict__ w_in, const float* __restrict__ b_in,
    const float* __restrict__ w_out,const float* __restrict__ b_out,
    const float* __restrict__ ln1g, const float* __restrict__ ln1b,
    const float* __restrict__ w1,   const float* __restrict__ b1,
    const float* __restrict__ w2,   const float* __restrict__ b2,
    const float* __restrict__ ln2g, const float* __restrict__ ln2b) {
    extern __shared__ float sm[];
    float* buf0 = sm;
    float* buf1 = sm + CHUNK_F;
    float* xs = sm + 2 * CHUNK_F;
    float* qs = xs + TPF;
    float* ks = xs + 2 * TPF;
    float* vs = xs + 3 * TPF;
    float* hs = xs + 4 * TPF;
    float* fs = xs + 5 * TPF;
    uint32_t bufu0 = smem_u32(buf0);
    uint32_t bufu1 = smem_u32(buf1);

    int t = threadIdx.x;
    int bid = blockIdx.x;
    int b = bid >> 1, s = bid & 1;
    int e = g_topi[b][s];
    float gate = g_topg[b][s];
    int tx = t & 15, ty = t >> 4;
    int na0 = ty * 2;

    // ---- prologue: start weight pipeline (chunks 0,1), overlap x load ----
    stage_next(0, bufu0, e, t, w_in, w_out, w1, w2);
    stage_next(1, bufu1, e, t, w_in, w_out, w1, w2);
    int c = 0;

    // ---- load x = concat(z, a) ----
    for (int i = t; i < NA * DD; i += 256) {
        int na = i >> 7, d = i & 127;
        float xv = (d < DZ) ? z[(b * NA + na) * DZ + d] : a[(b * NA + na) * DAA + (d - DZ)];
        xs[na * XP + d] = xv;
    }
    // (gemm_tile starts with cp_wait1 + __syncthreads — covers xs visibility)

    // ---- qkv = x @ wi^T + bi ----
    const float* bi = b_in + (size_t)e * 384;
    for (int tile = 0; tile < 3; tile++) {
        unsigned long long accp[16];
#pragma unroll
        for (int i = 0; i < 16; i++) accp[i] = 0ull;
        gemm_tile(c, bufu0, bufu1, buf0, buf1, xs, t, tx, na0, accp, e,
                  w_in, w_out, w1, w2);
        float* dst = (tile == 0) ? qs : (tile == 1) ? ks : vs;
#pragma unroll
        for (int r = 0; r < 2; r++)
#pragma unroll
            for (int j = 0; j < 8; j++) {
                int m = tx + 16 * j;
                dst[(na0 + r) * XP + m] = psum(accp[r * 8 + j]) + bi[tile * 128 + m];
            }
        __syncthreads();
    }

    // ---- attention scores (4 heads x 32 x 32) -> fs ----
    const float scale = 0.17677669529663687f;  // 1/sqrt(32)
    for (int i = t; i < 4096; i += 256) {
        int h = i >> 10, qi = (i >> 5) & 31, kj = i & 31;
        const float4* qp = reinterpret_cast<const float4*>(qs + qi * XP + h * 32);
        const float4* kp = reinterpret_cast<const float4*>(ks + kj * XP + h * 32);
        float acc = 0.f;
#pragma unroll
        for (int d = 0; d < 8; d++) {
            float4 qv = qp[d], kv = kp[d];
            acc += qv.x * kv.x + qv.y * kv.y + qv.z * kv.z + qv.w * kv.w;
        }
        fs[i] = acc * scale;
    }
    __syncthreads();
    // ---- softmax rows ----
    if (t < 128) {
        float* row = fs + t * 32;
        float m = row[0];
#pragma unroll
        for (int j = 1; j < 32; j++) m = fmaxf(m, row[j]);
        float ssum = 0.f;
#pragma unroll
        for (int j = 0; j < 32; j++) { float ee = expf(row[j] - m); row[j] = ee; ssum += ee; }
        float inv = 1.f / ssum;
#pragma unroll
        for (int j = 0; j < 32; j++) row[j] *= inv;
    }
    __syncthreads();
    // ---- o = att @ v  -> overwrite qs ----
    for (int i = t; i < 1024; i += 256) {
        int na = i >> 5, cg = i & 31;
        int h = cg >> 3, jl = (cg & 7) * 4;
        const float* ap = fs + (h * 32 + na) * 32;
        float4 acc4 = make_float4(0.f, 0.f, 0.f, 0.f);
#pragma unroll 8
        for (int k = 0; k < 32; k++) {
            float av = ap[k];
            float4 vv = *reinterpret_cast<const float4*>(vs + k * XP + h * 32 + jl);
            acc4.x += av * vv.x; acc4.y += av * vv.y;
            acc4.z += av * vv.z; acc4.w += av * vv.w;
        }
        *reinterpret_cast<float4*>(qs + na * XP + cg * 4) = acc4;
    }
    // (o-proj gemm starts with wait+sync — covers qs writes)

    // ---- o-proj + residual -> hs ----
    {
        unsigned long long accp[16];
#pragma unroll
        for (int i = 0; i < 16; i++) accp[i] = 0ull;
        gemm_tile(c, bufu0, bufu1, buf0, buf1, qs, t, tx, na0, accp, e,
                  w_in, w_out, w1, w2);
        const float* bo = b_out + (size_t)e * 128;
#pragma unroll
        for (int r = 0; r < 2; r++)
#pragma unroll
            for (int j = 0; j < 8; j++) {
                int m = tx + 16 * j;
                hs[(na0 + r) * XP + m] = psum(accp[r * 8 + j]) + bo[m] + xs[(na0 + r) * XP + m];
            }
    }
    __syncthreads();

    // ---- LN1 ----
    block_ln(hs, ln1g + (size_t)e * 128, ln1b + (size_t)e * 128, t);
    // (next gemm starts with wait+sync)

    // ---- FFN ----
    const float* B1 = b1 + (size_t)e * FF;
    const float* B2 = b2 + (size_t)e * DD;
    unsigned long long facc[16];
#pragma unroll
    for (int i = 0; i < 16; i++) facc[i] = 0ull;

    for (int ft = 0; ft < 8; ft++) {
        unsigned long long tacc[16];
#pragma unroll
        for (int i = 0; i < 16; i++) tacc[i] = 0ull;
        gemm_tile(c, bufu0, bufu1, buf0, buf1, hs, t, tx, na0, tacc, e,
                  w_in, w_out, w1, w2);
#pragma unroll
        for (int r = 0; r < 2; r++)
#pragma unroll
            for (int j = 0; j < 8; j++) {
                int m = tx + 16 * j;
                float v = psum(tacc[r * 8 + j]) + B1[ft * 128 + m];
                fs[(na0 + r) * XP + m] = fmaxf(v, 0.f);
            }
        // next gemm's wait+sync covers fs writes
        gemm_tile(c, bufu0, bufu1, buf0, buf1, fs, t, tx, na0, facc, e,
                  w_in, w_out, w1, w2);
    }

    // ---- epilogue: +bias +residual -> fs ----
#pragma unroll
    for (int r = 0; r < 2; r++)
#pragma unroll
        for (int j = 0; j < 8; j++) {
            int m = tx + 16 * j;
            fs[(na0 + r) * XP + m] = psum(facc[r * 8 + j]) + B2[m] + hs[(na0 + r) * XP + m];
        }
    __syncthreads();

    // ---- LN2, scale by gate, write to per-slot scratch ----
    {
        int w = t >> 5, lane = t & 31;
        const float* g2  = ln2g + (size_t)e * 128;
        const float* be2 = ln2b + (size_t)e * 128;
        for (int row = w; row < 32; row += 8) {
            float* base = fs + row * XP;
            float v0 = base[lane], v1 = base[lane + 32], v2 = base[lane + 64], v3 = base[lane + 96];
            float mu = warp_sum(v0 + v1 + v2 + v3) * (1.f / 128.f);
            float d0 = v0 - mu, d1 = v1 - mu, d2 = v2 - mu, d3 = v3 - mu;
            float var = warp_sum(d0 * d0 + d1 * d1 + d2 * d2 + d3 * d3) * (1.f / 128.f);
            float rs = rsqrtf(var + 1e-5f);
            float* outp = &g_yp[s][b][row * 128];
            outp[lane]      = (d0 * rs * g2[lane]      + be2[lane])      * gate;
            outp[lane + 32] = (d1 * rs * g2[lane + 32] + be2[lane + 32]) * gate;
            outp[lane + 64] = (d2 * rs * g2[lane + 64] + be2[lane + 64]) * gate;
            outp[lane + 96] = (d3 * rs * g2[lane + 96] + be2[lane + 96]) * gate;
        }
    }
}

// ============================ head ============================
// grid (64, 4): x = 16-token tile, y = 128-hidden tile. Staged weights + FFMA2.
#define HEAD_SMEM_FLOATS (128 * WPITCH + 16 * XP)
#define HEAD_SMEM_BYTES  (HEAD_SMEM_FLOATS * 4)

__global__ void __launch_bounds__(256, 2) head1_kernel(const float* __restrict__ hw1,
                                                       const float* __restrict__ hb1) {
    extern __shared__ float sm[];
    float* wsmem = sm;
    float* ys = sm + 128 * WPITCH;   // [16][XP]
    uint32_t wbase = smem_u32(wsmem);

    int t = threadIdx.x;
    int tok0 = blockIdx.x * 16;
    int hbase = blockIdx.y * 128;
    int tx = t & 15, ty = t >> 4;   // ty = token 0..15

    unsigned long long accp[8];
#pragma unroll
    for (int j = 0; j < 8; j++) accp[j] = 0ull;

    for (int kt = 0; kt < 32; kt++) {
        __syncthreads();   // wbuf + ys free for reuse
        const float* Wg = hw1 + (size_t)hbase * 4096 + kt * 128;
        stage_half(wbase, Wg, 4096, 0, t);
        stage_half(wbase, Wg, 4096, 16, t);
        // overlap ys fill with cp.async latency
        for (int i = t; i < 16 * 128; i += 256) {
            int tok = i >> 7, d = i & 127;
            int col = kt * 128 + d;
            ys[tok * XP + d] = g_yp[0][tok0 + tok][col] + g_yp[1][tok0 + tok][col];
        }
        cp_wait1();
        __syncthreads();
        const float* xr = ys + ty * XP;
#pragma unroll 4
        for (int dd = 0; dd < 64; dd += 4) {
            ulonglong2 xv = *reinterpret_cast<const ulonglong2*>(xr + dd);
#pragma unroll
            for (int j = 0; j < 8; j++) {
                ulonglong2 w = *reinterpret_cast<const ulonglong2*>(
                    wsmem + (tx + 16 * j) * WPITCH + dd);
                ffma2(accp[j], xv.x, w.x);
                ffma2(accp[j], xv.y, w.y);
            }
        }
        cp_wait0();
        __syncthreads();
#pragma unroll 4
        for (int dd = 64; dd < 128; dd += 4) {
            ulonglong2 xv = *reinterpret_cast<const ulonglong2*>(xr + dd);
#pragma unroll
            for (int j = 0; j < 8; j++) {
                ulonglong2 w = *reinterpret_cast<const ulonglong2*>(
                    wsmem + (tx + 16 * j) * WPITCH + dd);
                ffma2(accp[j], xv.x, w.x);
                ffma2(accp[j], xv.y, w.y);
            }
        }
    }
#pragma unroll
    for (int j = 0; j < 8; j++) {
        int hh = hbase + tx + 16 * j;
        g_h2[tok0 + ty][hh] = fmaxf(psum(accp[j]) + hb1[hh], 0.f);
    }
}

// grid BB, 128 threads: warp w computes output o=w for its token
__global__ void __launch_bounds__(128) head2_kernel(const float* __restrict__ hw2,
                                                    const float* __restrict__ hb2,
                                                    float* __restrict__ r_out) {
    int tok = blockIdx.x;
    int w = threadIdx.x >> 5, lane = threadIdx.x & 31;
    const float* hp = g_h2[tok];
    const float* wp = hw2 + (size_t)w * 512;
    float acc = 0.f;
#pragma unroll 4
    for (int j = lane; j < 512; j += 32) acc += hp[j] * wp[j];
    acc = warp_sum(acc);
    if (lane == 0) r_out[tok * 4 + w] = acc + hb2[w];
}

// ============================ loss ============================

__global__ void __launch_bounds__(256) loss_kernel(const float* __restrict__ gates,
                                                   float* __restrict__ loss_out) {
    int t = threadIdx.x;
    float imp[8], ld[8];
#pragma unroll
    for (int e = 0; e < 8; e++) { imp[e] = 0.f; ld[e] = 0.f; }
    float lsum = 0.f;
    for (int b = t; b < BB; b += 256) {
#pragma unroll
        for (int e = 0; e < 8; e++) {
            float g = gates[b * 8 + e];
            imp[e] += g;
            ld[e]  += (g > 0.f) ? 1.f : 0.f;
        }
        lsum += g_lse[b];
    }
    __shared__ float simp[8 * 8], sld[8 * 8], sls[8];
    int w = t >> 5, lane = t & 31;
#pragma unroll
    for (int e = 0; e < 8; e++) {
        float si = warp_sum(imp[e]);
        float sl = warp_sum(ld[e]);
        if (lane == 0) { simp[w * 8 + e] = si; sld[w * 8 + e] = sl; }
    }
    {
        float sl2 = warp_sum(lsum);
        if (lane == 0) sls[w] = sl2;
    }
    __syncthreads();
    if (t == 0) {
        float I[8], L[8];
        float ls = 0.f;
#pragma unroll
        for (int ww = 0; ww < 8; ww++) ls += sls[ww];
#pragma unroll
        for (int e = 0; e < 8; e++) {
            float si = 0.f, sl = 0.f;
#pragma unroll
            for (int ww = 0; ww < 8; ww++) { si += simp[ww * 8 + e]; sl += sld[ww * 8 + e]; }
            I[e] = si; L[e] = sl;
        }
        float mi = 0.f, ml = 0.f;
#pragma unroll
        for (int e = 0; e < 8; e++) { mi += I[e]; ml += L[e]; }
        mi *= (1.f / 8.f); ml *= (1.f / 8.f);
        float vi = 0.f, vl = 0.f;
#pragma unroll
        for (int e = 0; e < 8; e++) {
            vi += (I[e] - mi) * (I[e] - mi);
            vl += (L[e] - ml) * (L[e] - ml);
        }
        vi *= (1.f / 7.f); vl *= (1.f / 7.f);
        float cv2i = vi / (mi * mi + 1e-10f);
        float cv2l = vl / (ml * ml + 1e-10f);
        loss_out[0] = cv2i + cv2l + ls * (1.f / (float)BB);
    }
}

// ============================ launch ============================

extern "C" void kernel_launch(void* const* d_in, const int* in_sizes, int n_in,
                              void* d_out, int out_size) {
    const float* z      = (const float*)d_in[0];
    const float* a      = (const float*)d_in[1];
    const float* w_gate = (const float*)d_in[2];
    const float* w_in   = (const float*)d_in[3];
    const float* b_in   = (const float*)d_in[4];
    const float* w_out  = (const float*)d_in[5];
    const float* b_out  = (const float*)d_in[6];
    const float* ln1_g  = (const float*)d_in[7];
    const float* ln1_b  = (const float*)d_in[8];
    const float* w1     = (const float*)d_in[9];
    const float* b1     = (const float*)d_in[10];
    const float* w2     = (const float*)d_in[11];
    const float* b2     = (const float*)d_in[12];
    const float* ln2_g  = (const float*)d_in[13];
    const float* ln2_b  = (const float*)d_in[14];
    const float* hw1    = (const float*)d_in[15];
    const float* hb1    = (const float*)d_in[16];
    const float* hw2    = (const float*)d_in[17];
    const float* hb2    = (const float*)d_in[18];

    float* out       = (float*)d_out;
    float* r_out     = out;                    // [1024,4]
    float* gates_out = out + BB * 4;           // [1024,8]
    float* loss_out  = out + BB * 4 + BB * 8;  // scalar

    cudaFuncSetAttribute(expert_kernel, cudaFuncAttributeMaxDynamicSharedMemorySize,
                         EXPERT_SMEM_BYTES);
    cudaFuncSetAttribute(head1_kernel, cudaFuncAttributeMaxDynamicSharedMemorySize,
                         HEAD_SMEM_BYTES);

    router_kernel<<<BB, 256>>>(z, a, w_gate, gates_out);
    expert_kernel<<<BB * 2, 256, EXPERT_SMEM_BYTES>>>(z, a, w_in, b_in, w_out, b_out,
                                                      ln1_g, ln1_b, w1, b1, w2, b2,
                                                      ln2_g, ln2_b);
    head1_kernel<<<dim3(BB / 16, 4), 256, HEAD_SMEM_BYTES>>>(hw1, hb1);
    head2_kernel<<<BB, 128>>>(hw2, hb2, r_out);
    loss_kernel<<<1, 256>>>(gates_out, loss_out);
}

// round 12
// speedup vs baseline: 5.4204x; 1.0284x over previous
#include <cuda_runtime.h>
#include <math.h>
#include <stdint.h>

#define BB   1024
#define NA   32
#define DZ   96
#define DAA  32
#define DD   128
#define NE   8
#define FF   1024
#define XP   132    // activation tile pitch (floats)
#define WPITCH 132  // head1 staged weight row pitch (floats)
#define WB   528    // WPITCH*4
#define CPITCH 20   // expert chunk buffer row pitch (floats): 16 cols + 4 pad, 80B rows
#define CB   80     // CPITCH*4
#define CHUNK_F (128 * CPITCH)   // 2560 floats per chunk buffer
#define NCHUNKS 160 // 20 tiles x 8 sixteen-k subchunks

// -------- global scratch (no allocations allowed) --------
__device__ float g_yp[2][BB][NA * DD];   // per-slot expert outputs
__device__ float g_h2[BB][512];          // head hidden
__device__ int   g_topi[BB][2];
__device__ float g_topg[BB][2];
__device__ float g_lse[BB];

// ============================ helpers ============================

__device__ __forceinline__ uint32_t smem_u32(const void* p) {
    uint32_t r;
    asm("{ .reg .u64 t; cvta.to.shared.u64 t, %1; cvt.u32.u64 %0, t; }" : "=r"(r) : "l"(p));
    return r;
}
__device__ __forceinline__ void cp16(uint32_t dst, const void* src) {
    asm volatile("cp.async.ca.shared.global [%0], [%1], 16;" :: "r"(dst), "l"(src) : "memory");
}
__device__ __forceinline__ void cp_commit() {
    asm volatile("cp.async.commit_group;" ::: "memory");
}
__device__ __forceinline__ void cp_wait2() {
    asm volatile("cp.async.wait_group 2;" ::: "memory");
}
__device__ __forceinline__ void cp_wait1() {
    asm volatile("cp.async.wait_group 1;" ::: "memory");
}
__device__ __forceinline__ void cp_wait0() {
    asm volatile("cp.async.wait_group 0;" ::: "memory");
}

// packed f32x2 FMA: d.lo += a.lo*b.lo ; d.hi += a.hi*b.hi  (sm_103a FFMA2)
__device__ __forceinline__ void ffma2(unsigned long long& d,
                                      unsigned long long a, unsigned long long b) {
    asm("fma.rn.f32x2 %0, %1, %2, %0;" : "+l"(d) : "l"(a), "l"(b));
}
// horizontal sum of the two f32 lanes
__device__ __forceinline__ float psum(unsigned long long p) {
    float lo, hi;
    asm("mov.b64 {%0,%1}, %2;" : "=f"(lo), "=f"(hi) : "l"(p));
    return lo + hi;
}

__device__ __forceinline__ float warp_sum(float s) {
#pragma unroll
    for (int off = 16; off; off >>= 1) s += __shfl_xor_sync(0xffffffffu, s, off);
    return s;
}

// ---- head1 staging (full 128-col buffer, WPITCH rows) ----
__device__ __forceinline__ void stage_half(uint32_t wbase, const float* __restrict__ Wg,
                                           int ldw, int dqoff, int t) {
    for (int i = t; i < 2048; i += 256) {
        int m = i >> 4;
        int dq = (i & 15) + dqoff;
        cp16(wbase + m * WB + dq * 16, Wg + (size_t)m * ldw + dq * 4);
    }
    cp_commit();
}

// ---- expert: stage chunk cidx (tile cidx>>3, 16-col sub cidx&7) ----
__device__ __forceinline__ void stage_next(int cidx, uint32_t dstbase, int e, int t,
                                           const float* __restrict__ w_in,
                                           const float* __restrict__ w_out,
                                           const float* __restrict__ w1,
                                           const float* __restrict__ w2) {
    if (cidx < NCHUNKS) {
        int tile = cidx >> 3, sub = cidx & 7;
        const float* p;
        int ldw;
        if (tile < 3)       { p = w_in  + (size_t)e * 384 * 128 + (size_t)tile * 16384; ldw = 128; }
        else if (tile == 3) { p = w_out + (size_t)e * 16384; ldw = 128; }
        else if ((tile & 1) == 0) { int ft = (tile - 4) >> 1;
                              p = w1 + (size_t)e * FF * DD + (size_t)ft * 16384; ldw = 128; }
        else                { int ft = (tile - 4) >> 1;
                              p = w2 + (size_t)e * DD * FF + ft * 128; ldw = FF; }
        p += sub * 16;
        for (int i = t; i < 512; i += 256) {
            int m = i >> 2, dq = i & 3;
            cp16(dstbase + m * CB + dq * 16, p + (size_t)m * ldw + dq * 4);
        }
    }
    cp_commit();   // empty group past NCHUNKS keeps accounting uniform
}

// packed 16-k sub-GEMM: accp[r*8+j] lanes hold (even-k, odd-k) partial sums
__device__ __forceinline__ void mm_sub(const float* __restrict__ xs, int xoff,
                                       const float* __restrict__ wb,
                                       int na0, int tx, unsigned long long accp[16]) {
    const float* xr0 = xs + na0 * XP + xoff;
    const float* xr1 = xr0 + XP;
#pragma unroll
    for (int dd = 0; dd < 16; dd += 4) {
        ulonglong2 x0 = *reinterpret_cast<const ulonglong2*>(xr0 + dd);
        ulonglong2 x1 = *reinterpret_cast<const ulonglong2*>(xr1 + dd);
#pragma unroll
        for (int j = 0; j < 8; j++) {
            ulonglong2 w = *reinterpret_cast<const ulonglong2*>(wb + (tx + 16 * j) * CPITCH + dd);
            ffma2(accp[j],     x0.x, w.x);
            ffma2(accp[j],     x0.y, w.y);
            ffma2(accp[8 + j], x1.x, w.x);
            ffma2(accp[8 + j], x1.y, w.y);
        }
    }
}

// one 128-k GEMM tile = 8 sub-chunks through a 3-buffer rotating prefetch ring
__device__ __forceinline__ void gemm_tile(int& c, int& bs,
                                          uint32_t bufu0, uint32_t bufu1, uint32_t bufu2,
                                          const float* __restrict__ buf0,
                                          const float* __restrict__ buf1,
                                          const float* __restrict__ buf2,
                                          const float* __restrict__ xsrc,
                                          int t, int tx, int na0,
                                          unsigned long long accp[16], int e,
                                          const float* __restrict__ w_in,
                                          const float* __restrict__ w_out,
                                          const float* __restrict__ w1,
                                          const float* __restrict__ w2) {
#pragma unroll
    for (int h = 0; h < 8; h++) {
        cp_wait2();          // chunks <= c complete (two newest groups may be in flight)
        __syncthreads();
        const float* wb = (bs == 0) ? buf0 : (bs == 1) ? buf1 : buf2;
        mm_sub(xsrc, h * 16, wb, na0, tx, accp);
        __syncthreads();     // all readers done before refill
        uint32_t du = (bs == 0) ? bufu0 : (bs == 1) ? bufu1 : bufu2;
        stage_next(c + 3, du, e, t, w_in, w_out, w1, w2);
        c++;
        bs = (bs == 2) ? 0 : bs + 1;
    }
}

// in-place layernorm over rows of buf[32][XP] (D=128), 8 warps / 32 rows
__device__ __forceinline__ void block_ln(float* buf, const float* __restrict__ g,
                                         const float* __restrict__ bt, int t) {
    int w = t >> 5, lane = t & 31;
    for (int row = w; row < 32; row += 8) {
        float* base = buf + row * XP;
        float v0 = base[lane], v1 = base[lane + 32], v2 = base[lane + 64], v3 = base[lane + 96];
        float mu = warp_sum(v0 + v1 + v2 + v3) * (1.f / 128.f);
        float d0 = v0 - mu, d1 = v1 - mu, d2 = v2 - mu, d3 = v3 - mu;
        float var = warp_sum(d0 * d0 + d1 * d1 + d2 * d2 + d3 * d3) * (1.f / 128.f);
        float rs = rsqrtf(var + 1e-5f);
        base[lane]      = d0 * rs * g[lane]      + bt[lane];
        base[lane + 32] = d1 * rs * g[lane + 32] + bt[lane + 32];
        base[lane + 64] = d2 * rs * g[lane + 64] + bt[lane + 64];
        base[lane + 96] = d3 * rs * g[lane + 96] + bt[lane + 96];
    }
}

// ============================ router ============================

__global__ void __launch_bounds__(256) router_kernel(const float* __restrict__ z,
                                                     const float* __restrict__ a,
                                                     const float* __restrict__ wg,
                                                     float* __restrict__ gates_out) {
    int b = blockIdx.x, t = threadIdx.x;
    float acc[8];
#pragma unroll
    for (int e = 0; e < 8; e++) acc[e] = 0.f;

    for (int i = t; i < NA * DD; i += 256) {
        int na = i >> 7, d = i & 127;
        float xv = (d < DZ) ? z[(b * NA + na) * DZ + d] : a[(b * NA + na) * DAA + (d - DZ)];
        const float4* wr = reinterpret_cast<const float4*>(wg + (size_t)i * 8);
        float4 w0 = wr[0], w1 = wr[1];
        acc[0] += xv * w0.x; acc[1] += xv * w0.y; acc[2] += xv * w0.z; acc[3] += xv * w0.w;
        acc[4] += xv * w1.x; acc[5] += xv * w1.y; acc[6] += xv * w1.z; acc[7] += xv * w1.w;
    }

    __shared__ float sred[8 * 8];
    __shared__ float lgs[8];
    int w = t >> 5, lane = t & 31;
#pragma unroll
    for (int e = 0; e < 8; e++) {
        float s = warp_sum(acc[e]);
        if (lane == 0) sred[w * 8 + e] = s;
    }
    __syncthreads();
    if (t < 8) {
        float s = 0.f;
#pragma unroll
        for (int ww = 0; ww < 8; ww++) s += sred[ww * 8 + t];
        lgs[t] = s;
    }
    __syncthreads();
    if (t == 0) {
        float m = lgs[0];
#pragma unroll
        for (int e = 1; e < 8; e++) m = fmaxf(m, lgs[e]);
        float se = 0.f;
#pragma unroll
        for (int e = 0; e < 8; e++) se += expf(lgs[e] - m);
        g_lse[b] = logf(se) + m;

        int i0 = 0; float v0 = lgs[0];
#pragma unroll
        for (int e = 1; e < 8; e++) if (lgs[e] > v0) { v0 = lgs[e]; i0 = e; }
        int i1 = -1; float v1 = -1e30f;
#pragma unroll
        for (int e = 0; e < 8; e++) if (e != i0 && lgs[e] > v1) { v1 = lgs[e]; i1 = e; }

        float ex = expf(v1 - v0);
        float inv = 1.f / (1.f + ex);
        float g0 = inv, g1 = ex * inv;
#pragma unroll
        for (int e = 0; e < 8; e++) gates_out[b * 8 + e] = 0.f;
        gates_out[b * 8 + i0] = g0;
        gates_out[b * 8 + i1] = g1;
        g_topi[b][0] = i0; g_topi[b][1] = i1;
        g_topg[b][0] = g0; g_topg[b][1] = g1;
    }
}

// ============================ expert ============================
// smem: 3 chunk buffers (16-k, CPITCH 20) + 5 activation buffers [32][XP]
// hs aliases ks (k dead after scores; hs first written at o-proj epilogue)
#define TPF (32 * XP)
#define EXPERT_SMEM_FLOATS (3 * CHUNK_F + 5 * TPF)   // 7680 + 21120 = 28800 -> 115200 B
#define EXPERT_SMEM_BYTES  (EXPERT_SMEM_FLOATS * 4)

__global__ void __launch_bounds__(256, 2) expert_kernel(
    const float* __restrict__ z,    const float* __restrict__ a,
    const float* __restrict__ w_in, const float* __restrict__ b_in,
    const float* __restrict__ w_out,const float* __restrict__ b_out,
    const float* __restrict__ ln1g, const float* __restrict__ ln1b,
    const float* __restrict__ w1,   const float* __restrict__ b1,
    const float* __restrict__ w2,   const float* __restrict__ b2,
    const float* __restrict__ ln2g, const float* __restrict__ ln2b) {
    extern __shared__ float sm[];
    float* buf0 = sm;
    float* buf1 = sm + CHUNK_F;
    float* buf2 = sm + 2 * CHUNK_F;
    float* xs = sm + 3 * CHUNK_F;
    float* qs = xs + TPF;
    float* ks = xs + 2 * TPF;
    float* vs = xs + 3 * TPF;
    float* fs = xs + 4 * TPF;
    float* hs = ks;                 // alias: k dead before hs is born
    uint32_t bufu0 = smem_u32(buf0);
    uint32_t bufu1 = smem_u32(buf1);
    uint32_t bufu2 = smem_u32(buf2);

    int t = threadIdx.x;
    int bid = blockIdx.x;
    int b = bid >> 1, s = bid & 1;
    int e = g_topi[b][s];
    float gate = g_topg[b][s];
    int tx = t & 15, ty = t >> 4;
    int na0 = ty * 2;

    // ---- prologue: start weight pipeline (chunks 0,1,2), overlap x load ----
    stage_next(0, bufu0, e, t, w_in, w_out, w1, w2);
    stage_next(1, bufu1, e, t, w_in, w_out, w1, w2);
    stage_next(2, bufu2, e, t, w_in, w_out, w1, w2);
    int c = 0, bs = 0;

    // ---- load x = concat(z, a) ----
    for (int i = t; i < NA * DD; i += 256) {
        int na = i >> 7, d = i & 127;
        float xv = (d < DZ) ? z[(b * NA + na) * DZ + d] : a[(b * NA + na) * DAA + (d - DZ)];
        xs[na * XP + d] = xv;
    }
    // (gemm_tile starts with cp_wait + __syncthreads — covers xs visibility)

    // ---- qkv = x @ wi^T + bi ----
    const float* bi = b_in + (size_t)e * 384;
    for (int tile = 0; tile < 3; tile++) {
        unsigned long long accp[16];
#pragma unroll
        for (int i = 0; i < 16; i++) accp[i] = 0ull;
        gemm_tile(c, bs, bufu0, bufu1, bufu2, buf0, buf1, buf2, xs,
                  t, tx, na0, accp, e, w_in, w_out, w1, w2);
        float* dst = (tile == 0) ? qs : (tile == 1) ? ks : vs;
#pragma unroll
        for (int r = 0; r < 2; r++)
#pragma unroll
            for (int j = 0; j < 8; j++) {
                int m = tx + 16 * j;
                dst[(na0 + r) * XP + m] = psum(accp[r * 8 + j]) + bi[tile * 128 + m];
            }
        __syncthreads();
    }

    // ---- attention scores (4 heads x 32 x 32) -> fs ----
    const float scale = 0.17677669529663687f;  // 1/sqrt(32)
    for (int i = t; i < 4096; i += 256) {
        int h = i >> 10, qi = (i >> 5) & 31, kj = i & 31;
        const float4* qp = reinterpret_cast<const float4*>(qs + qi * XP + h * 32);
        const float4* kp = reinterpret_cast<const float4*>(ks + kj * XP + h * 32);
        float acc = 0.f;
#pragma unroll
        for (int d = 0; d < 8; d++) {
            float4 qv = qp[d], kv = kp[d];
            acc += qv.x * kv.x + qv.y * kv.y + qv.z * kv.z + qv.w * kv.w;
        }
        fs[i] = acc * scale;
    }
    __syncthreads();
    // ---- softmax rows ----
    if (t < 128) {
        float* row = fs + t * 32;
        float m = row[0];
#pragma unroll
        for (int j = 1; j < 32; j++) m = fmaxf(m, row[j]);
        float ssum = 0.f;
#pragma unroll
        for (int j = 0; j < 32; j++) { float ee = expf(row[j] - m); row[j] = ee; ssum += ee; }
        float inv = 1.f / ssum;
#pragma unroll
        for (int j = 0; j < 32; j++) row[j] *= inv;
    }
    __syncthreads();
    // ---- o = att @ v  -> overwrite qs ----
    for (int i = t; i < 1024; i += 256) {
        int na = i >> 5, cg = i & 31;
        int h = cg >> 3, jl = (cg & 7) * 4;
        const float* ap = fs + (h * 32 + na) * 32;
        float4 acc4 = make_float4(0.f, 0.f, 0.f, 0.f);
#pragma unroll 8
        for (int k = 0; k < 32; k++) {
            float av = ap[k];
            float4 vv = *reinterpret_cast<const float4*>(vs + k * XP + h * 32 + jl);
            acc4.x += av * vv.x; acc4.y += av * vv.y;
            acc4.z += av * vv.z; acc4.w += av * vv.w;
        }
        *reinterpret_cast<float4*>(qs + na * XP + cg * 4) = acc4;
    }
    // (o-proj gemm starts with wait+sync — covers qs writes; ks reads all done)

    // ---- o-proj + residual -> hs (= ks) ----
    {
        unsigned long long accp[16];
#pragma unroll
        for (int i = 0; i < 16; i++) accp[i] = 0ull;
        gemm_tile(c, bs, bufu0, bufu1, bufu2, buf0, buf1, buf2, qs,
                  t, tx, na0, accp, e, w_in, w_out, w1, w2);
        const float* bo = b_out + (size_t)e * 128;
#pragma unroll
        for (int r = 0; r < 2; r++)
#pragma unroll
            for (int j = 0; j < 8; j++) {
                int m = tx + 16 * j;
                hs[(na0 + r) * XP + m] = psum(accp[r * 8 + j]) + bo[m] + xs[(na0 + r) * XP + m];
            }
    }
    __syncthreads();

    // ---- LN1 ----
    block_ln(hs, ln1g + (size_t)e * 128, ln1b + (size_t)e * 128, t);
    // (next gemm starts with wait+sync)

    // ---- FFN ----
    const float* B1 = b1 + (size_t)e * FF;
    const float* B2 = b2 + (size_t)e * DD;
    unsigned long long facc[16];
#pragma unroll
    for (int i = 0; i < 16; i++) facc[i] = 0ull;

    for (int ft = 0; ft < 8; ft++) {
        unsigned long long tacc[16];
#pragma unroll
        for (int i = 0; i < 16; i++) tacc[i] = 0ull;
        gemm_tile(c, bs, bufu0, bufu1, bufu2, buf0, buf1, buf2, hs,
                  t, tx, na0, tacc, e, w_in, w_out, w1, w2);
#pragma unroll
        for (int r = 0; r < 2; r++)
#pragma unroll
            for (int j = 0; j < 8; j++) {
                int m = tx + 16 * j;
                float v = psum(tacc[r * 8 + j]) + B1[ft * 128 + m];
                fs[(na0 + r) * XP + m] = fmaxf(v, 0.f);
            }
        // next gemm's wait+sync covers fs writes
        gemm_tile(c, bs, bufu0, bufu1, bufu2, buf0, buf1, buf2, fs,
                  t, tx, na0, facc, e, w_in, w_out, w1, w2);
    }

    // ---- epilogue: +bias +residual -> fs ----
#pragma unroll
    for (int r = 0; r < 2; r++)
#pragma unroll
        for (int j = 0; j < 8; j++) {
            int m = tx + 16 * j;
            fs[(na0 + r) * XP + m] = psum(facc[r * 8 + j]) + B2[m] + hs[(na0 + r) * XP + m];
        }
    __syncthreads();

    // ---- LN2, scale by gate, write to per-slot scratch ----
    {
        int w = t >> 5, lane = t & 31;
        const float* g2  = ln2g + (size_t)e * 128;
        const float* be2 = ln2b + (size_t)e * 128;
        for (int row = w; row < 32; row += 8) {
            float* base = fs + row * XP;
            float v0 = base[lane], v1 = base[lane + 32], v2 = base[lane + 64], v3 = base[lane + 96];
            float mu = warp_sum(v0 + v1 + v2 + v3) * (1.f / 128.f);
            float d0 = v0 - mu, d1 = v1 - mu, d2 = v2 - mu, d3 = v3 - mu;
            float var = warp_sum(d0 * d0 + d1 * d1 + d2 * d2 + d3 * d3) * (1.f / 128.f);
            float rs = rsqrtf(var + 1e-5f);
            float* outp = &g_yp[s][b][row * 128];
            outp[lane]      = (d0 * rs * g2[lane]      + be2[lane])      * gate;
            outp[lane + 32] = (d1 * rs * g2[lane + 32] + be2[lane + 32]) * gate;
            outp[lane + 64] = (d2 * rs * g2[lane + 64] + be2[lane + 64]) * gate;
            outp[lane + 96] = (d3 * rs * g2[lane + 96] + be2[lane + 96]) * gate;
        }
    }
}

// ============================ head ============================
// grid (64, 4): x = 16-token tile, y = 128-hidden tile. Staged weights + FFMA2.
#define HEAD_SMEM_FLOATS (128 * WPITCH + 16 * XP)
#define HEAD_SMEM_BYTES  (HEAD_SMEM_FLOATS * 4)

__global__ void __launch_bounds__(256, 2) head1_kernel(const float* __restrict__ hw1,
                                                       const float* __restrict__ hb1) {
    extern __shared__ float sm[];
    float* wsmem = sm;
    float* ys = sm + 128 * WPITCH;   // [16][XP]
    uint32_t wbase = smem_u32(wsmem);

    int t = threadIdx.x;
    int tok0 = blockIdx.x * 16;
    int hbase = blockIdx.y * 128;
    int tx = t & 15, ty = t >> 4;   // ty = token 0..15

    unsigned long long accp[8];
#pragma unroll
    for (int j = 0; j < 8; j++) accp[j] = 0ull;

    for (int kt = 0; kt < 32; kt++) {
        __syncthreads();   // wbuf + ys free for reuse
        const float* Wg = hw1 + (size_t)hbase * 4096 + kt * 128;
        stage_half(wbase, Wg, 4096, 0, t);
        stage_half(wbase, Wg, 4096, 16, t);
        // overlap ys fill with cp.async latency
        for (int i = t; i < 16 * 128; i += 256) {
            int tok = i >> 7, d = i & 127;
            int col = kt * 128 + d;
            ys[tok * XP + d] = g_yp[0][tok0 + tok][col] + g_yp[1][tok0 + tok][col];
        }
        cp_wait1();
        __syncthreads();
        const float* xr = ys + ty * XP;
#pragma unroll 4
        for (int dd = 0; dd < 64; dd += 4) {
            ulonglong2 xv = *reinterpret_cast<const ulonglong2*>(xr + dd);
#pragma unroll
            for (int j = 0; j < 8; j++) {
                ulonglong2 w = *reinterpret_cast<const ulonglong2*>(
                    wsmem + (tx + 16 * j) * WPITCH + dd);
                ffma2(accp[j], xv.x, w.x);
                ffma2(accp[j], xv.y, w.y);
            }
        }
        cp_wait0();
        __syncthreads();
#pragma unroll 4
        for (int dd = 64; dd < 128; dd += 4) {
            ulonglong2 xv = *reinterpret_cast<const ulonglong2*>(xr + dd);
#pragma unroll
            for (int j = 0; j < 8; j++) {
                ulonglong2 w = *reinterpret_cast<const ulonglong2*>(
                    wsmem + (tx + 16 * j) * WPITCH + dd);
                ffma2(accp[j], xv.x, w.x);
                ffma2(accp[j], xv.y, w.y);
            }
        }
    }
#pragma unroll
    for (int j = 0; j < 8; j++) {
        int hh = hbase + tx + 16 * j;
        g_h2[tok0 + ty][hh] = fmaxf(psum(accp[j]) + hb1[hh], 0.f);
    }
}

// grid BB, 128 threads: warp w computes output o=w for its token
__global__ void __launch_bounds__(128) head2_kernel(const float* __restrict__ hw2,
                                                    const float* __restrict__ hb2,
                                                    float* __restrict__ r_out) {
    int tok = blockIdx.x;
    int w = threadIdx.x >> 5, lane = threadIdx.x & 31;
    const float* hp = g_h2[tok];
    const float* wp = hw2 + (size_t)w * 512;
    float acc = 0.f;
#pragma unroll 4
    for (int j = lane; j < 512; j += 32) acc += hp[j] * wp[j];
    acc = warp_sum(acc);
    if (lane == 0) r_out[tok * 4 + w] = acc + hb2[w];
}

// ============================ loss ============================

__global__ void __launch_bounds__(256) loss_kernel(const float* __restrict__ gates,
                                                   float* __restrict__ loss_out) {
    int t = threadIdx.x;
    float imp[8], ld[8];
#pragma unroll
    for (int e = 0; e < 8; e++) { imp[e] = 0.f; ld[e] = 0.f; }
    float lsum = 0.f;
    for (int b = t; b < BB; b += 256) {
#pragma unroll
        for (int e = 0; e < 8; e++) {
            float g = gates[b * 8 + e];
            imp[e] += g;
            ld[e]  += (g > 0.f) ? 1.f : 0.f;
        }
        lsum += g_lse[b];
    }
    __shared__ float simp[8 * 8], sld[8 * 8], sls[8];
    int w = t >> 5, lane = t & 31;
#pragma unroll
    for (int e = 0; e < 8; e++) {
        float si = warp_sum(imp[e]);
        float sl = warp_sum(ld[e]);
        if (lane == 0) { simp[w * 8 + e] = si; sld[w * 8 + e] = sl; }
    }
    {
        float sl2 = warp_sum(lsum);
        if (lane == 0) sls[w] = sl2;
    }
    __syncthreads();
    if (t == 0) {
        float I[8], L[8];
        float ls = 0.f;
#pragma unroll
        for (int ww = 0; ww < 8; ww++) ls += sls[ww];
#pragma unroll
        for (int e = 0; e < 8; e++) {
            float si = 0.f, sl = 0.f;
#pragma unroll
            for (int ww = 0; ww < 8; ww++) { si += simp[ww * 8 + e]; sl += sld[ww * 8 + e]; }
            I[e] = si; L[e] = sl;
        }
        float mi = 0.f, ml = 0.f;
#pragma unroll
        for (int e = 0; e < 8; e++) { mi += I[e]; ml += L[e]; }
        mi *= (1.f / 8.f); ml *= (1.f / 8.f);
        float vi = 0.f, vl = 0.f;
#pragma unroll
        for (int e = 0; e < 8; e++) {
            vi += (I[e] - mi) * (I[e] - mi);
            vl += (L[e] - ml) * (L[e] - ml);
        }
        vi *= (1.f / 7.f); vl *= (1.f / 7.f);
        float cv2i = vi / (mi * mi + 1e-10f);
        float cv2l = vl / (ml * ml + 1e-10f);
        loss_out[0] = cv2i + cv2l + ls * (1.f / (float)BB);
    }
}

// ============================ launch ============================

extern "C" void kernel_launch(void* const* d_in, const int* in_sizes, int n_in,
                              void* d_out, int out_size) {
    const float* z      = (const float*)d_in[0];
    const float* a      = (const float*)d_in[1];
    const float* w_gate = (const float*)d_in[2];
    const float* w_in   = (const float*)d_in[3];
    const float* b_in   = (const float*)d_in[4];
    const float* w_out  = (const float*)d_in[5];
    const float* b_out  = (const float*)d_in[6];
    const float* ln1_g  = (const float*)d_in[7];
    const float* ln1_b  = (const float*)d_in[8];
    const float* w1     = (const float*)d_in[9];
    const float* b1     = (const float*)d_in[10];
    const float* w2     = (const float*)d_in[11];
    const float* b2     = (const float*)d_in[12];
    const float* ln2_g  = (const float*)d_in[13];
    const float* ln2_b  = (const float*)d_in[14];
    const float* hw1    = (const float*)d_in[15];
    const float* hb1    = (const float*)d_in[16];
    const float* hw2    = (const float*)d_in[17];
    const float* hb2    = (const float*)d_in[18];

    float* out       = (float*)d_out;
    float* r_out     = out;                    // [1024,4]
    float* gates_out = out + BB * 4;           // [1024,8]
    float* loss_out  = out + BB * 4 + BB * 8;  // scalar

    cudaFuncSetAttribute(expert_kernel, cudaFuncAttributeMaxDynamicSharedMemorySize,
                         EXPERT_SMEM_BYTES);
    cudaFuncSetAttribute(head1_kernel, cudaFuncAttributeMaxDynamicSharedMemorySize,
                         HEAD_SMEM_BYTES);

    router_kernel<<<BB, 256>>>(z, a, w_gate, gates_out);
    expert_kernel<<<BB * 2, 256, EXPERT_SMEM_BYTES>>>(z, a, w_in, b_in, w_out, b_out,
                                                      ln1_g, ln1_b, w1, b1, w2, b2,
                                                      ln2_g, ln2_b);
    head1_kernel<<<dim3(BB / 16, 4), 256, HEAD_SMEM_BYTES>>>(hw1, hb1);
    head2_kernel<<<BB, 128>>>(hw2, hb2, r_out);
    loss_kernel<<<1, 256>>>(gates_out, loss_out);
}